// round 10
// baseline (speedup 1.0000x reference)
#include <cuda_runtime.h>
#include <cuda_fp16.h>
#include <math.h>
#include <stdint.h>

#define BATCH 4
#define SEQ   2048
#define DIM   768
#define NH    12
#define DKH   64
#define DFF   3072
#define TOK   (BATCH*SEQ)   // 8192
#define QKVN  (3*DIM)       // 2304

// ---------------- scratch (device globals; no runtime allocation) -------------------
__device__ __half g_h16  [TOK*DIM];
__device__ __half g_qkv16[(size_t)TOK*QKVN];
__device__ __half g_att16[TOK*DIM];
__device__ float  g_x1   [(size_t)TOK*DIM];
__device__ __half g_ff16 [(size_t)TOK*DFF];
__device__ __half g_qkvw [QKVN*DIM];      // [2304,768] fp16 (W^T)
__device__ __half g_wo   [DIM*DIM];       // [768,768]
__device__ __half g_wg   [2*DFF*DIM];     // [6144,768] (val/gate interleaved per 8 rows)
__device__ __half g_wout [DIM*DFF];       // [768,3072]

// ---------------- PTX helpers (baseline ISA: cp.async, ldmatrix, mma.sync) ----------
__device__ __forceinline__ uint32_t smem_u32(const void* p) {
    uint32_t a;
    asm("{ .reg .u64 t; cvta.to.shared.u64 t, %1; cvt.u32.u64 %0, t; }" : "=r"(a) : "l"(p));
    return a;
}
#define CP16(sa, gp) asm volatile("cp.async.cg.shared.global [%0], [%1], 16;\n" :: "r"(sa), "l"(gp))
#define CP_COMMIT()  asm volatile("cp.async.commit_group;\n" ::: "memory")
#define CP_WAIT(n)   asm volatile("cp.async.wait_group %0;\n" :: "n"(n) : "memory")

#define LDMX4(r, addr) \
    asm volatile("ldmatrix.sync.aligned.m8n8.x4.shared.b16 {%0,%1,%2,%3}, [%4];" \
        : "=r"((r)[0]), "=r"((r)[1]), "=r"((r)[2]), "=r"((r)[3]) : "r"(addr))
#define LDMX4T(r, addr) \
    asm volatile("ldmatrix.sync.aligned.m8n8.x4.trans.shared.b16 {%0,%1,%2,%3}, [%4];" \
        : "=r"((r)[0]), "=r"((r)[1]), "=r"((r)[2]), "=r"((r)[3]) : "r"(addr))

#define MMA16816(d, a, b0, b1) \
    asm volatile("mma.sync.aligned.m16n8k16.row.col.f32.f16.f16.f32 " \
        "{%0,%1,%2,%3}, {%4,%5,%6,%7}, {%8,%9}, {%0,%1,%2,%3};" \
        : "+f"((d)[0]), "+f"((d)[1]), "+f"((d)[2]), "+f"((d)[3]) \
        : "r"((a)[0]), "r"((a)[1]), "r"((a)[2]), "r"((a)[3]), "r"(b0), "r"(b1))

// ---------------- fused weight prep: all 6 transposes in one launch ------------------
__global__ void wtrans_all(const float* __restrict__ Wq, const float* __restrict__ Wk,
                           const float* __restrict__ Wv, const float* __restrict__ Wo,
                           const float* __restrict__ Wg, const float* __restrict__ Wout_,
                           __half* __restrict__ qkvw, __half* __restrict__ wo16,
                           __half* __restrict__ wg16, __half* __restrict__ wout16) {
    int bid = blockIdx.x;
    const float* W; __half* Wt; int K, N, bx, by, perm = 0;
    if (bid < 1728) {                       // Wq, Wk, Wv -> qkvw
        int m = bid / 576, r = bid % 576;
        W = (m == 0) ? Wq : (m == 1) ? Wk : Wv;
        Wt = qkvw + (size_t)m * DIM * DIM; K = DIM; N = DIM;
        bx = r % 24; by = r / 24;
    } else if (bid < 2304) {                // Wo
        int r = bid - 1728; W = Wo; Wt = wo16; K = DIM; N = DIM;
        bx = r % 24; by = r / 24;
    } else if (bid < 6912) {                // Wg (permuted)
        int r = bid - 2304; W = Wg; Wt = wg16; K = DIM; N = 2 * DFF; perm = 1;
        bx = r % 192; by = r / 192;
    } else {                                // Wout
        int r = bid - 6912; W = Wout_; Wt = wout16; K = DFF; N = DIM;
        bx = r % 24; by = r / 24;
    }
    __shared__ float tile[32][33];
    int k0 = by * 32, n0 = bx * 32;
    int tx = threadIdx.x, ty = threadIdx.y;
    #pragma unroll
    for (int i = ty; i < 32; i += 8)
        tile[i][tx] = W[(size_t)(k0 + i) * N + n0 + tx];
    __syncthreads();
    #pragma unroll
    for (int i = ty; i < 32; i += 8) {
        int n = n0 + i, dr;
        if (perm) {
            int isg = n >= DFF;
            int sp = isg ? n - DFF : n;
            dr = (sp >> 3) * 16 + (isg << 3) + (sp & 7);
        } else dr = n;
        Wt[(size_t)dr * K + k0 + tx] = __float2half_rn(tile[tx][i]);
    }
}

// ---------------- LayerNorm -> fp16 ---------------------------------------------------
__global__ void ln_kernel(const float* __restrict__ x, const float* __restrict__ g,
                          const float* __restrict__ b, __half* __restrict__ out) {
    int row = blockIdx.x;
    int tid = threadIdx.x;
    const float* xr = x + (size_t)row * DIM;
    float s1 = 0.f, s2 = 0.f;
    for (int i = tid; i < DIM; i += 256) { float v = xr[i]; s1 += v; s2 += v*v; }
    #pragma unroll
    for (int o = 16; o; o >>= 1) {
        s1 += __shfl_xor_sync(0xffffffffu, s1, o);
        s2 += __shfl_xor_sync(0xffffffffu, s2, o);
    }
    __shared__ float r1[8], r2[8];
    if ((tid & 31) == 0) { r1[tid >> 5] = s1; r2[tid >> 5] = s2; }
    __syncthreads();
    if (tid < 32) {
        s1 = (tid < 8) ? r1[tid] : 0.f;
        s2 = (tid < 8) ? r2[tid] : 0.f;
        #pragma unroll
        for (int o = 4; o; o >>= 1) {
            s1 += __shfl_xor_sync(0xffffffffu, s1, o);
            s2 += __shfl_xor_sync(0xffffffffu, s2, o);
        }
        if (tid == 0) { r1[0] = s1; r2[0] = s2; }
    }
    __syncthreads();
    float mu  = r1[0] * (1.f / DIM);
    float var = r2[0] * (1.f / DIM) - mu * mu;
    float inv = rsqrtf(var + 1e-5f);
    __half* outr = out + (size_t)row * DIM;
    for (int i = tid; i < DIM; i += 256)
        outr[i] = __float2half_rn((xr[i] - mu) * inv * g[i] + b[i]);
}

// ---------------- HMMA fp16 GEMM (persistent tiles) -----------------------------------
// C[M,N] = A16[M,K] @ Bt16[N,K]^T. CTA tile 128x128, 8 warps (2m x 4n), warp 64x32.
// 3-stage cp.async pipeline, one barrier per chunk. Grid is one full wave (2 CTA/SM);
// each CTA loops over output tiles -> no wave-quantization tail.
// QSCALE=1: cols < DIM scaled by 0.125. GEGLU=1: (val+b)*gelu(gate+b) -> fp16.
template<int OUTH, int BIAS, int RES, int GEGLU, int QSCALE>
__global__ void __launch_bounds__(256, 2)
gemm16(const __half* __restrict__ A, const __half* __restrict__ Bt,
       const float* __restrict__ bias, const float* __restrict__ res,
       void* __restrict__ Cout, int N, int K, int nbx, int ntiles) {
    extern __shared__ char sm[];
    uint32_t BUF = smem_u32(sm);          // stage s at BUF + s*32768: A(16K) B(16K)
    int tid = threadIdx.x, wid = tid >> 5, lane = tid & 31;
    int wm = (wid >> 2) * 64, wn = (wid & 3) * 32;
    const int NK = K >> 6;
    const int lr = tid >> 3;    // 0..31
    const int lc = tid & 7;     // 16B chunk in 128B row
    int groupId = lane >> 2, t4 = lane & 3;

    for (int t = blockIdx.x; t < ntiles; t += gridDim.x) {
        __syncthreads();   // previous tile fully consumed before stages are refilled
        const int bm = (t / nbx) * 128, bn = (t % nbx) * 128;

        float acc[4][4][4] = {};

        // prologue: chunks 0 and 1 -> stages 0 and 1
        #pragma unroll
        for (int s = 0; s < 2; s++) {
            const __half* Ag = A  + (size_t)(bm + lr) * K + (size_t)s * 64 + lc * 8;
            const __half* Bg = Bt + (size_t)(bn + lr) * K + (size_t)s * 64 + lc * 8;
            uint32_t sa = BUF + s * 32768u;
            #pragma unroll
            for (int l = 0; l < 4; l++) {
                int r = lr + l * 32;
                uint32_t soff = r * 128 + ((lc ^ (r & 7)) << 4);
                CP16(sa + soff,         Ag + (size_t)l * 32 * K);
                CP16(sa + 16384 + soff, Bg + (size_t)l * 32 * K);
            }
            CP_COMMIT();
        }

        for (int kc = 0; kc < NK; kc++) {
            if (kc + 1 < NK) { CP_WAIT(1); } else { CP_WAIT(0); }
            __syncthreads();
            if (kc + 2 < NK) {
                int st = (kc + 2) % 3;
                const __half* Ag = A  + (size_t)(bm + lr) * K + (size_t)(kc + 2) * 64 + lc * 8;
                const __half* Bg = Bt + (size_t)(bn + lr) * K + (size_t)(kc + 2) * 64 + lc * 8;
                uint32_t sa = BUF + st * 32768u;
                #pragma unroll
                for (int l = 0; l < 4; l++) {
                    int r = lr + l * 32;
                    uint32_t soff = r * 128 + ((lc ^ (r & 7)) << 4);
                    CP16(sa + soff,         Ag + (size_t)l * 32 * K);
                    CP16(sa + 16384 + soff, Bg + (size_t)l * 32 * K);
                }
                CP_COMMIT();
            }

            uint32_t Ab = BUF + (kc % 3) * 32768u;
            uint32_t Bb = Ab + 16384u;
            #pragma unroll
            for (int ks = 0; ks < 4; ks++) {
                uint32_t af[4][4];
                #pragma unroll
                for (int mt = 0; mt < 4; mt++) {
                    int r = wm + mt * 16 + (lane & 15);
                    int c = ks * 2 + (lane >> 4);
                    LDMX4(af[mt], Ab + r * 128 + ((c ^ (r & 7)) << 4));
                }
                uint32_t bf[2][4];
                #pragma unroll
                for (int nt = 0; nt < 2; nt++) {
                    int r = wn + nt * 16 + (lane & 15);
                    int c = ks * 2 + (lane >> 4);
                    LDMX4(bf[nt], Bb + r * 128 + ((c ^ (r & 7)) << 4));
                }
                #pragma unroll
                for (int mt = 0; mt < 4; mt++) {
                    #pragma unroll
                    for (int n8 = 0; n8 < 4; n8++) {
                        uint32_t b0 = bf[n8 >> 1][n8 & 1];
                        uint32_t b1 = bf[n8 >> 1][(n8 & 1) + 2];
                        MMA16816(acc[mt][n8], af[mt], b0, b1);
                    }
                }
            }
        }

        if (GEGLU) {
            #pragma unroll
            for (int mt = 0; mt < 4; mt++) {
                #pragma unroll
                for (int n8 = 0; n8 < 4; n8 += 2) {
                    float* dv = acc[mt][n8];
                    float* dg = acc[mt][n8 + 1];
                    int colp = bn + wn + n8 * 8;
                    int cout = ((colp >> 4) << 3) + t4 * 2;
                    float bv0 = bias[cout],       bv1 = bias[cout + 1];
                    float bg0 = bias[DFF + cout], bg1 = bias[DFF + cout + 1];
                    #pragma unroll
                    for (int h2 = 0; h2 < 2; h2++) {
                        int row = bm + wm + mt * 16 + groupId + h2 * 8;
                        float v0 = dv[h2 * 2] + bv0, v1 = dv[h2 * 2 + 1] + bv1;
                        float g0 = dg[h2 * 2] + bg0, g1 = dg[h2 * 2 + 1] + bg1;
                        float f0 = v0 * 0.5f * g0 * (1.f + erff(g0 * 0.70710678118654752f));
                        float f1 = v1 * 0.5f * g1 * (1.f + erff(g1 * 0.70710678118654752f));
                        *(__half2*)((__half*)Cout + (size_t)row * DFF + cout) = __floats2half2_rn(f0, f1);
                    }
                }
            }
        } else {
            #pragma unroll
            for (int mt = 0; mt < 4; mt++) {
                #pragma unroll
                for (int n8 = 0; n8 < 4; n8++) {
                    float* d = acc[mt][n8];
                    int col = bn + wn + n8 * 8 + t4 * 2;
                    #pragma unroll
                    for (int h2 = 0; h2 < 2; h2++) {
                        int row = bm + wm + mt * 16 + groupId + h2 * 8;
                        float v0 = d[h2 * 2], v1 = d[h2 * 2 + 1];
                        if (BIAS) { v0 += bias[col]; v1 += bias[col + 1]; }
                        if (RES) {
                            float2 rv = *(const float2*)(res + (size_t)row * N + col);
                            v0 += rv.x; v1 += rv.y;
                        }
                        if (QSCALE && col < DIM) { v0 *= 0.125f; v1 *= 0.125f; }
                        if (OUTH) {
                            *(__half2*)((__half*)Cout + (size_t)row * N + col) = __floats2half2_rn(v0, v1);
                        } else {
                            *(float2*)((float*)Cout + (size_t)row * N + col) = make_float2(v0, v1);
                        }
                    }
                }
            }
        }
    }
}

// ---------------- Flash attention, fp16 HMMA, causal, BQ=128 --------------------------
// 256 threads, 8 warps x 16 q-rows. BK=64. SMEM (64KB):
// Qs 16K | Ks[2] 16K | Vs[2] 16K | Ps 16K. Q pre-scaled by 0.125 (folded into QKV GEMM).
__global__ void __launch_bounds__(256)
attn_kernel(const __half* __restrict__ QKV, __half* __restrict__ O16) {
    extern __shared__ char sm[];
    uint32_t SB = smem_u32(sm);
    const uint32_t SQ = SB;              // 16384
    const uint32_t SK = SB + 16384;      // + kb*8192
    const uint32_t SV = SB + 32768;      // + kb*8192
    const uint32_t SP = SB + 49152;      // 16384

    int qt = blockIdx.x;                 // 0..15
    int bh = blockIdx.y;
    int h = bh % NH, b = bh / NH;
    int q0 = qt * 128;
    int tid = threadIdx.x, wid = tid >> 5, lane = tid & 31;
    int wm = wid * 16;                   // 0..112
    int groupId = lane >> 2, t4 = lane & 3;
    const size_t qbase = (size_t)b * SEQ * QKVN + (size_t)h * DKH;

    int lr8 = tid >> 3, lc = tid & 7;    // lr8 0..31

    // Q tile (128 rows) + KV tile 0 (64 rows), single group
    #pragma unroll
    for (int l = 0; l < 4; l++) {
        int r = lr8 + l * 32;
        uint32_t soff = r * 128 + ((lc ^ (r & 7)) << 4);
        CP16(SQ + soff, QKV + qbase + (size_t)(q0 + r) * QKVN + lc * 8);
    }
    #pragma unroll
    for (int l = 0; l < 2; l++) {
        int r = lr8 + l * 32;
        uint32_t soff = r * 128 + ((lc ^ (r & 7)) << 4);
        const __half* gp = QKV + qbase + (size_t)r * QKVN + lc * 8;
        CP16(SK + soff, gp + DIM);
        CP16(SV + soff, gp + 2 * DIM);
    }
    CP_COMMIT();

    float m0 = -1e30f, m1 = -1e30f, l0 = 0.f, l1 = 0.f;
    float oacc[8][4] = {};
    const int ktmax = 2 * qt + 1;

    for (int kt = 0; kt <= ktmax; kt++) {
        int kb = kt & 1;
        CP_WAIT(0);
        __syncthreads();   // publishes KV kt; all warps done with buffer kb^1
        if (kt < ktmax) {
            int nb = kb ^ 1;
            int k0n = (kt + 1) * 64;
            #pragma unroll
            for (int l = 0; l < 2; l++) {
                int r = lr8 + l * 32;
                uint32_t soff = r * 128 + ((lc ^ (r & 7)) << 4);
                const __half* gp = QKV + qbase + (size_t)(k0n + r) * QKVN + lc * 8;
                CP16(SK + nb * 8192 + soff, gp + DIM);
                CP16(SV + nb * 8192 + soff, gp + 2 * DIM);
            }
            CP_COMMIT();
        }

        uint32_t Kb = SK + kb * 8192;
        uint32_t Vb = SV + kb * 8192;

        // ---- S = Q @ K^T (Q pre-scaled) ----
        float sacc[8][4] = {};
        #pragma unroll
        for (int ks = 0; ks < 4; ks++) {
            uint32_t af[4];
            {
                int r = wm + (lane & 15);
                int c = ks * 2 + (lane >> 4);
                LDMX4(af, SQ + r * 128 + ((c ^ (r & 7)) << 4));
            }
            uint32_t bf[4][4];
            #pragma unroll
            for (int nt = 0; nt < 4; nt++) {
                int r = nt * 16 + (lane & 15);
                int c = ks * 2 + (lane >> 4);
                LDMX4(bf[nt], Kb + r * 128 + ((c ^ (r & 7)) << 4));
            }
            #pragma unroll
            for (int j = 0; j < 8; j++)
                MMA16816(sacc[j], af, bf[j >> 1][j & 1], bf[j >> 1][(j & 1) + 2]);
        }

        int lr0 = wm + groupId, lr1 = lr0 + 8;   // rows relative to q0
        int off = kt * 64 - q0;                  // col base relative to q0
        if (off + 63 > wm) {   // this warp's rows may be masked
            #pragma unroll
            for (int j = 0; j < 8; j++) {
                int c0 = off + j * 8 + t4 * 2;
                if (c0     > lr0) sacc[j][0] = -1e30f;
                if (c0 + 1 > lr0) sacc[j][1] = -1e30f;
                if (c0     > lr1) sacc[j][2] = -1e30f;
                if (c0 + 1 > lr1) sacc[j][3] = -1e30f;
            }
        }

        float mx0 = -1e30f, mx1 = -1e30f;
        #pragma unroll
        for (int j = 0; j < 8; j++) {
            mx0 = fmaxf(mx0, fmaxf(sacc[j][0], sacc[j][1]));
            mx1 = fmaxf(mx1, fmaxf(sacc[j][2], sacc[j][3]));
        }
        mx0 = fmaxf(mx0, __shfl_xor_sync(0xffffffffu, mx0, 1));
        mx0 = fmaxf(mx0, __shfl_xor_sync(0xffffffffu, mx0, 2));
        mx1 = fmaxf(mx1, __shfl_xor_sync(0xffffffffu, mx1, 1));
        mx1 = fmaxf(mx1, __shfl_xor_sync(0xffffffffu, mx1, 2));

        float mn0 = fmaxf(m0, mx0), mn1 = fmaxf(m1, mx1);
        float c0f = __expf(m0 - mn0), c1f = __expf(m1 - mn1);
        float s0 = 0.f, s1 = 0.f;
        #pragma unroll
        for (int j = 0; j < 8; j++) {
            float p0 = __expf(sacc[j][0] - mn0);
            float p1 = __expf(sacc[j][1] - mn0);
            float p2 = __expf(sacc[j][2] - mn1);
            float p3 = __expf(sacc[j][3] - mn1);
            s0 += p0 + p1; s1 += p2 + p3;
            uint32_t a0 = SP + lr0 * 128 + (((j ^ (lr0 & 7))) << 4) + t4 * 4;
            uint32_t a1 = SP + lr1 * 128 + (((j ^ (lr1 & 7))) << 4) + t4 * 4;
            *(__half2*)(sm + (a0 - SB)) = __floats2half2_rn(p0, p1);
            *(__half2*)(sm + (a1 - SB)) = __floats2half2_rn(p2, p3);
        }
        s0 += __shfl_xor_sync(0xffffffffu, s0, 1);
        s0 += __shfl_xor_sync(0xffffffffu, s0, 2);
        s1 += __shfl_xor_sync(0xffffffffu, s1, 1);
        s1 += __shfl_xor_sync(0xffffffffu, s1, 2);
        l0 = l0 * c0f + s0; m0 = mn0;
        l1 = l1 * c1f + s1; m1 = mn1;
        #pragma unroll
        for (int j = 0; j < 8; j++) {
            oacc[j][0] *= c0f; oacc[j][1] *= c0f;
            oacc[j][2] *= c1f; oacc[j][3] *= c1f;
        }
        __syncwarp();

        // ---- O += P @ V ----
        #pragma unroll
        for (int ks2 = 0; ks2 < 4; ks2++) {
            uint32_t pf[4];
            {
                int r = wm + (lane & 15);
                int c = ks2 * 2 + (lane >> 4);
                LDMX4(pf, SP + r * 128 + ((c ^ (r & 7)) << 4));
            }
            uint32_t vf[4][4];
            #pragma unroll
            for (int nt = 0; nt < 4; nt++) {
                int r = ks2 * 16 + (lane & 15);
                int c = nt * 2 + (lane >> 4);
                LDMX4T(vf[nt], Vb + r * 128 + ((c ^ (r & 7)) << 4));
            }
            #pragma unroll
            for (int j = 0; j < 8; j++)
                MMA16816(oacc[j], pf, vf[j >> 1][2 * (j & 1)], vf[j >> 1][2 * (j & 1) + 1]);
        }
    }

    const size_t obase = ((size_t)b * SEQ + q0) * DIM + (size_t)h * DKH;
    float inv0 = 1.f / l0, inv1 = 1.f / l1;
    int lr0 = wm + groupId, lr1 = lr0 + 8;
    #pragma unroll
    for (int j = 0; j < 8; j++) {
        int col = j * 8 + t4 * 2;
        *(__half2*)(O16 + obase + (size_t)lr0 * DIM + col) =
            __floats2half2_rn(oacc[j][0] * inv0, oacc[j][1] * inv0);
        *(__half2*)(O16 + obase + (size_t)lr1 * DIM + col) =
            __floats2half2_rn(oacc[j][2] * inv1, oacc[j][3] * inv1);
    }
}

// ---------------- launch --------------------------------------------------------------
extern "C" void kernel_launch(void* const* d_in, const int* in_sizes, int n_in,
                              void* d_out, int out_size) {
    const float* x     = (const float*)d_in[0];
    const float* ln1_g = (const float*)d_in[2];
    const float* ln1_b = (const float*)d_in[3];
    const float* ln2_g = (const float*)d_in[4];
    const float* ln2_b = (const float*)d_in[5];
    const float* Wq    = (const float*)d_in[6];
    const float* Wk    = (const float*)d_in[7];
    const float* Wv    = (const float*)d_in[8];
    const float* Wo    = (const float*)d_in[9];
    const float* Wg    = (const float*)d_in[10];
    const float* bg    = (const float*)d_in[11];
    const float* Wout  = (const float*)d_in[12];
    float* out = (float*)d_out;

    __half *h16, *qkv16, *att16, *ff16, *qkvw, *wo16, *wg16, *wout16;
    float *x1;
    cudaGetSymbolAddress((void**)&h16,    g_h16);
    cudaGetSymbolAddress((void**)&qkv16,  g_qkv16);
    cudaGetSymbolAddress((void**)&att16,  g_att16);
    cudaGetSymbolAddress((void**)&x1,     g_x1);
    cudaGetSymbolAddress((void**)&ff16,   g_ff16);
    cudaGetSymbolAddress((void**)&qkvw,   g_qkvw);
    cudaGetSymbolAddress((void**)&wo16,   g_wo);
    cudaGetSymbolAddress((void**)&wg16,   g_wg);
    cudaGetSymbolAddress((void**)&wout16, g_wout);

    const int ATTN_SMEM = 65536;
    const int GEMM_SMEM = 3 * 32768;   // 98304 (3-stage)
    const int GRID_P    = 296;         // 2 CTAs/SM x 148 SMs: one full wave
    cudaFuncSetAttribute(attn_kernel, cudaFuncAttributeMaxDynamicSharedMemorySize, ATTN_SMEM);
    cudaFuncSetAttribute(gemm16<1,0,0,0,1>, cudaFuncAttributeMaxDynamicSharedMemorySize, GEMM_SMEM);
    cudaFuncSetAttribute(gemm16<0,0,1,0,0>, cudaFuncAttributeMaxDynamicSharedMemorySize, GEMM_SMEM);
    cudaFuncSetAttribute(gemm16<1,0,0,1,0>, cudaFuncAttributeMaxDynamicSharedMemorySize, GEMM_SMEM);

    // weight prep: one launch (9216 blocks; Wg rows permuted for GeGLU fusion)
    wtrans_all<<<9216, dim3(32, 8)>>>(Wq, Wk, Wv, Wo, Wg, Wout,
                                      qkvw, wo16, wg16, wout16);

    // attention sublayer (pre-LN); QKV GEMM scales Q columns by 0.125
    ln_kernel<<<TOK, 256>>>(x, ln1_g, ln1_b, h16);
    gemm16<1,0,0,0,1><<<GRID_P, 256, GEMM_SMEM>>>(h16, qkvw, nullptr, nullptr, qkv16,
                                                  QKVN, DIM, QKVN/128, (QKVN/128)*(TOK/128));
    attn_kernel<<<dim3(SEQ/128, BATCH*NH), 256, ATTN_SMEM>>>(qkv16, att16);
    gemm16<0,0,1,0,0><<<GRID_P, 256, GEMM_SMEM>>>(att16, wo16, nullptr, x, x1,
                                                  DIM, DIM, DIM/128, (DIM/128)*(TOK/128));

    // GeGLU FFN sublayer (pre-LN); Wg GEMM fuses bias + GeGLU, writes ff16 directly
    ln_kernel<<<TOK, 256>>>(x1, ln2_g, ln2_b, h16);
    gemm16<1,0,0,1,0><<<GRID_P, 256, GEMM_SMEM>>>(h16, wg16, bg, nullptr, ff16,
                                                  2*DFF, DIM, 2*DFF/128, (2*DFF/128)*(TOK/128));
    gemm16<0,0,1,0,0><<<GRID_P, 256, GEMM_SMEM>>>(ff16, wout16, nullptr, x1, out,
                                                  DIM, DFF, DIM/128, (DIM/128)*(TOK/128));
}

// round 11
// speedup vs baseline: 1.0504x; 1.0504x over previous
#include <cuda_runtime.h>
#include <cuda_fp16.h>
#include <math.h>
#include <stdint.h>

#define BATCH 4
#define SEQ   2048
#define DIM   768
#define NH    12
#define DKH   64
#define DFF   3072
#define TOK   (BATCH*SEQ)   // 8192
#define QKVN  (3*DIM)       // 2304

// ---------------- scratch (device globals; no runtime allocation) -------------------
__device__ __half g_h16  [TOK*DIM];
__device__ __half g_qkv16[(size_t)TOK*QKVN];
__device__ __half g_att16[TOK*DIM];
__device__ float  g_x1   [(size_t)TOK*DIM];
__device__ __half g_ff16 [(size_t)TOK*DFF];
__device__ __half g_qkvw [QKVN*DIM];      // [2304,768] fp16 (W^T)
__device__ __half g_wo   [DIM*DIM];       // [768,768]
__device__ __half g_wg   [2*DFF*DIM];     // [6144,768] (val/gate interleaved per 8 rows)
__device__ __half g_wout [DIM*DFF];       // [768,3072]

// ---------------- PTX helpers (baseline ISA: cp.async, ldmatrix, mma.sync) ----------
__device__ __forceinline__ uint32_t smem_u32(const void* p) {
    uint32_t a;
    asm("{ .reg .u64 t; cvta.to.shared.u64 t, %1; cvt.u32.u64 %0, t; }" : "=r"(a) : "l"(p));
    return a;
}
#define CP16(sa, gp) asm volatile("cp.async.cg.shared.global [%0], [%1], 16;\n" :: "r"(sa), "l"(gp))
#define CP_COMMIT()  asm volatile("cp.async.commit_group;\n" ::: "memory")
#define CP_WAIT(n)   asm volatile("cp.async.wait_group %0;\n" :: "n"(n) : "memory")

#define LDMX4(r, addr) \
    asm volatile("ldmatrix.sync.aligned.m8n8.x4.shared.b16 {%0,%1,%2,%3}, [%4];" \
        : "=r"((r)[0]), "=r"((r)[1]), "=r"((r)[2]), "=r"((r)[3]) : "r"(addr))
#define LDMX4T(r, addr) \
    asm volatile("ldmatrix.sync.aligned.m8n8.x4.trans.shared.b16 {%0,%1,%2,%3}, [%4];" \
        : "=r"((r)[0]), "=r"((r)[1]), "=r"((r)[2]), "=r"((r)[3]) : "r"(addr))

#define MMA16816(d, a, b0, b1) \
    asm volatile("mma.sync.aligned.m16n8k16.row.col.f32.f16.f16.f32 " \
        "{%0,%1,%2,%3}, {%4,%5,%6,%7}, {%8,%9}, {%0,%1,%2,%3};" \
        : "+f"((d)[0]), "+f"((d)[1]), "+f"((d)[2]), "+f"((d)[3]) \
        : "r"((a)[0]), "r"((a)[1]), "r"((a)[2]), "r"((a)[3]), "r"(b0), "r"(b1))

// ---------------- fused weight prep: all 6 transposes in one launch ------------------
__global__ void wtrans_all(const float* __restrict__ Wq, const float* __restrict__ Wk,
                           const float* __restrict__ Wv, const float* __restrict__ Wo,
                           const float* __restrict__ Wg, const float* __restrict__ Wout_,
                           __half* __restrict__ qkvw, __half* __restrict__ wo16,
                           __half* __restrict__ wg16, __half* __restrict__ wout16) {
    int bid = blockIdx.x;
    const float* W; __half* Wt; int K, N, bx, by, perm = 0;
    if (bid < 1728) {                       // Wq, Wk, Wv -> qkvw
        int m = bid / 576, r = bid % 576;
        W = (m == 0) ? Wq : (m == 1) ? Wk : Wv;
        Wt = qkvw + (size_t)m * DIM * DIM; K = DIM; N = DIM;
        bx = r % 24; by = r / 24;
    } else if (bid < 2304) {                // Wo
        int r = bid - 1728; W = Wo; Wt = wo16; K = DIM; N = DIM;
        bx = r % 24; by = r / 24;
    } else if (bid < 6912) {                // Wg (permuted)
        int r = bid - 2304; W = Wg; Wt = wg16; K = DIM; N = 2 * DFF; perm = 1;
        bx = r % 192; by = r / 192;
    } else {                                // Wout
        int r = bid - 6912; W = Wout_; Wt = wout16; K = DFF; N = DIM;
        bx = r % 24; by = r / 24;
    }
    __shared__ float tile[32][33];
    int k0 = by * 32, n0 = bx * 32;
    int tx = threadIdx.x, ty = threadIdx.y;
    #pragma unroll
    for (int i = ty; i < 32; i += 8)
        tile[i][tx] = W[(size_t)(k0 + i) * N + n0 + tx];
    __syncthreads();
    #pragma unroll
    for (int i = ty; i < 32; i += 8) {
        int n = n0 + i, dr;
        if (perm) {
            int isg = n >= DFF;
            int sp = isg ? n - DFF : n;
            dr = (sp >> 3) * 16 + (isg << 3) + (sp & 7);
        } else dr = n;
        Wt[(size_t)dr * K + k0 + tx] = __float2half_rn(tile[tx][i]);
    }
}

// ---------------- LayerNorm -> fp16 ---------------------------------------------------
__global__ void ln_kernel(const float* __restrict__ x, const float* __restrict__ g,
                          const float* __restrict__ b, __half* __restrict__ out) {
    int row = blockIdx.x;
    int tid = threadIdx.x;
    const float* xr = x + (size_t)row * DIM;
    float s1 = 0.f, s2 = 0.f;
    for (int i = tid; i < DIM; i += 256) { float v = xr[i]; s1 += v; s2 += v*v; }
    #pragma unroll
    for (int o = 16; o; o >>= 1) {
        s1 += __shfl_xor_sync(0xffffffffu, s1, o);
        s2 += __shfl_xor_sync(0xffffffffu, s2, o);
    }
    __shared__ float r1[8], r2[8];
    if ((tid & 31) == 0) { r1[tid >> 5] = s1; r2[tid >> 5] = s2; }
    __syncthreads();
    if (tid < 32) {
        s1 = (tid < 8) ? r1[tid] : 0.f;
        s2 = (tid < 8) ? r2[tid] : 0.f;
        #pragma unroll
        for (int o = 4; o; o >>= 1) {
            s1 += __shfl_xor_sync(0xffffffffu, s1, o);
            s2 += __shfl_xor_sync(0xffffffffu, s2, o);
        }
        if (tid == 0) { r1[0] = s1; r2[0] = s2; }
    }
    __syncthreads();
    float mu  = r1[0] * (1.f / DIM);
    float var = r2[0] * (1.f / DIM) - mu * mu;
    float inv = rsqrtf(var + 1e-5f);
    __half* outr = out + (size_t)row * DIM;
    for (int i = tid; i < DIM; i += 256)
        outr[i] = __float2half_rn((xr[i] - mu) * inv * g[i] + b[i]);
}

// ---------------- HMMA fp16 GEMM: C[M,N] = A16[M,K] @ Bt16[N,K]^T ---------------------
// CTA tile 128x128, 8 warps (2m x 4n), warp tile 64x32, K-chunk 64.
// 3-stage cp.async pipeline, one barrier per chunk.
// QSCALE=1: cols < DIM scaled by 0.125. GEGLU=1: (val+b)*gelu(gate+b) -> fp16.
template<int OUTH, int BIAS, int RES, int GEGLU, int QSCALE>
__global__ void __launch_bounds__(256, 2)
gemm16(const __half* __restrict__ A, const __half* __restrict__ Bt,
       const float* __restrict__ bias, const float* __restrict__ res,
       void* __restrict__ Cout, int N, int K) {
    extern __shared__ char sm[];
    uint32_t BUF = smem_u32(sm);          // stage s at BUF + s*32768: A(16K) B(16K)
    const int bm = blockIdx.y * 128, bn = blockIdx.x * 128;
    int tid = threadIdx.x, wid = tid >> 5, lane = tid & 31;
    int wm = (wid >> 2) * 64, wn = (wid & 3) * 32;

    const int NK = K >> 6;
    const int lr = tid >> 3;    // 0..31
    const int lc = tid & 7;     // 16B chunk in 128B row

    float acc[4][4][4] = {};

    // prologue: chunks 0 and 1 -> stages 0 and 1
    #pragma unroll
    for (int s = 0; s < 2; s++) {
        const __half* Ag = A  + (size_t)(bm + lr) * K + (size_t)s * 64 + lc * 8;
        const __half* Bg = Bt + (size_t)(bn + lr) * K + (size_t)s * 64 + lc * 8;
        uint32_t sa = BUF + s * 32768u;
        #pragma unroll
        for (int l = 0; l < 4; l++) {
            int r = lr + l * 32;
            uint32_t soff = r * 128 + ((lc ^ (r & 7)) << 4);
            CP16(sa + soff,         Ag + (size_t)l * 32 * K);
            CP16(sa + 16384 + soff, Bg + (size_t)l * 32 * K);
        }
        CP_COMMIT();
    }

    for (int kc = 0; kc < NK; kc++) {
        if (kc + 1 < NK) { CP_WAIT(1); } else { CP_WAIT(0); }
        __syncthreads();   // publishes chunk kc; all warps done with chunk kc-1
        if (kc + 2 < NK) {
            int st = (kc + 2) % 3;
            const __half* Ag = A  + (size_t)(bm + lr) * K + (size_t)(kc + 2) * 64 + lc * 8;
            const __half* Bg = Bt + (size_t)(bn + lr) * K + (size_t)(kc + 2) * 64 + lc * 8;
            uint32_t sa = BUF + st * 32768u;
            #pragma unroll
            for (int l = 0; l < 4; l++) {
                int r = lr + l * 32;
                uint32_t soff = r * 128 + ((lc ^ (r & 7)) << 4);
                CP16(sa + soff,         Ag + (size_t)l * 32 * K);
                CP16(sa + 16384 + soff, Bg + (size_t)l * 32 * K);
            }
            CP_COMMIT();
        }

        uint32_t Ab = BUF + (kc % 3) * 32768u;
        uint32_t Bb = Ab + 16384u;
        #pragma unroll
        for (int ks = 0; ks < 4; ks++) {
            uint32_t af[4][4];
            #pragma unroll
            for (int mt = 0; mt < 4; mt++) {
                int r = wm + mt * 16 + (lane & 15);
                int c = ks * 2 + (lane >> 4);
                LDMX4(af[mt], Ab + r * 128 + ((c ^ (r & 7)) << 4));
            }
            uint32_t bf[2][4];
            #pragma unroll
            for (int nt = 0; nt < 2; nt++) {
                int r = wn + nt * 16 + (lane & 15);
                int c = ks * 2 + (lane >> 4);
                LDMX4(bf[nt], Bb + r * 128 + ((c ^ (r & 7)) << 4));
            }
            #pragma unroll
            for (int mt = 0; mt < 4; mt++) {
                #pragma unroll
                for (int n8 = 0; n8 < 4; n8++) {
                    uint32_t b0 = bf[n8 >> 1][n8 & 1];
                    uint32_t b1 = bf[n8 >> 1][(n8 & 1) + 2];
                    MMA16816(acc[mt][n8], af[mt], b0, b1);
                }
            }
        }
    }

    int groupId = lane >> 2, t4 = lane & 3;
    if (GEGLU) {
        // fragment n8 even = val cols, n8 odd = gate cols for the same output cols
        #pragma unroll
        for (int mt = 0; mt < 4; mt++) {
            #pragma unroll
            for (int n8 = 0; n8 < 4; n8 += 2) {
                float* dv = acc[mt][n8];
                float* dg = acc[mt][n8 + 1];
                int colp = bn + wn + n8 * 8;             // permuted base, multiple of 16
                int cout = ((colp >> 4) << 3) + t4 * 2;  // output col in [0,DFF)
                float bv0 = bias[cout],       bv1 = bias[cout + 1];
                float bg0 = bias[DFF + cout], bg1 = bias[DFF + cout + 1];
                #pragma unroll
                for (int h2 = 0; h2 < 2; h2++) {
                    int row = bm + wm + mt * 16 + groupId + h2 * 8;
                    float v0 = dv[h2 * 2] + bv0, v1 = dv[h2 * 2 + 1] + bv1;
                    float g0 = dg[h2 * 2] + bg0, g1 = dg[h2 * 2 + 1] + bg1;
                    float f0 = v0 * 0.5f * g0 * (1.f + erff(g0 * 0.70710678118654752f));
                    float f1 = v1 * 0.5f * g1 * (1.f + erff(g1 * 0.70710678118654752f));
                    *(__half2*)((__half*)Cout + (size_t)row * DFF + cout) = __floats2half2_rn(f0, f1);
                }
            }
        }
        return;
    }
    #pragma unroll
    for (int mt = 0; mt < 4; mt++) {
        #pragma unroll
        for (int n8 = 0; n8 < 4; n8++) {
            float* d = acc[mt][n8];
            int col = bn + wn + n8 * 8 + t4 * 2;
            #pragma unroll
            for (int h2 = 0; h2 < 2; h2++) {
                int row = bm + wm + mt * 16 + groupId + h2 * 8;
                float v0 = d[h2 * 2], v1 = d[h2 * 2 + 1];
                if (BIAS) { v0 += bias[col]; v1 += bias[col + 1]; }
                if (RES) {
                    float2 rv = *(const float2*)(res + (size_t)row * N + col);
                    v0 += rv.x; v1 += rv.y;
                }
                if (QSCALE && col < DIM) { v0 *= 0.125f; v1 *= 0.125f; }
                if (OUTH) {
                    *(__half2*)((__half*)Cout + (size_t)row * N + col) = __floats2half2_rn(v0, v1);
                } else {
                    *(float2*)((float*)Cout + (size_t)row * N + col) = make_float2(v0, v1);
                }
            }
        }
    }
}

// ---------------- Flash attention, fp16 HMMA, causal, BQ=BK=64 ------------------------
// 4 warps x 16 q-rows. SMEM (40KB): Qs 8K | Ks[2] 16K | Vs[2] 16K. P stays in
// registers: the m16n8k16 C fragment packed to half2 IS the next A fragment
// (a = {pack(pj0[0,1]), pack(pj0[2,3]), pack(pj1[0,1]), pack(pj1[2,3])}).
// Q pre-scaled by 0.125 (folded into QKV GEMM). One barrier per kt iteration.
__global__ void __launch_bounds__(128)
attn_kernel(const __half* __restrict__ QKV, __half* __restrict__ O16) {
    extern __shared__ char sm[];
    uint32_t SB = smem_u32(sm);
    const uint32_t SQ = SB;
    const uint32_t SK = SB + 8192;      // + kb*8192
    const uint32_t SV = SB + 24576;     // + kb*8192

    int qt = blockIdx.x;
    int bh = blockIdx.y;
    int h = bh % NH, b = bh / NH;
    int q0 = qt * 64;
    int tid = threadIdx.x, wid = tid >> 5, lane = tid & 31;
    int wm = wid * 16;
    int groupId = lane >> 2, t4 = lane & 3;
    const size_t qbase = (size_t)b * SEQ * QKVN + (size_t)h * DKH;

    int lr8 = tid >> 3, lc = tid & 7;

    // Q tile + KV tile 0 (single group)
    #pragma unroll
    for (int l = 0; l < 4; l++) {
        int r = lr8 + l * 16;
        uint32_t soff = r * 128 + ((lc ^ (r & 7)) << 4);
        CP16(SQ + soff, QKV + qbase + (size_t)(q0 + r) * QKVN + lc * 8);
    }
    #pragma unroll
    for (int l = 0; l < 4; l++) {
        int r = lr8 + l * 16;
        uint32_t soff = r * 128 + ((lc ^ (r & 7)) << 4);
        const __half* gp = QKV + qbase + (size_t)r * QKVN + lc * 8;
        CP16(SK + soff, gp + DIM);
        CP16(SV + soff, gp + 2 * DIM);
    }
    CP_COMMIT();

    float m0 = -1e30f, m1 = -1e30f, l0 = 0.f, l1 = 0.f;
    float oacc[8][4] = {};

    for (int kt = 0; kt <= qt; kt++) {
        int kb = kt & 1;
        CP_WAIT(0);
        __syncthreads();   // publishes KV kt; all warps done with buffer kb^1
        if (kt < qt) {
            int nb = kb ^ 1;
            int k0n = (kt + 1) * 64;
            #pragma unroll
            for (int l = 0; l < 4; l++) {
                int r = lr8 + l * 16;
                uint32_t soff = r * 128 + ((lc ^ (r & 7)) << 4);
                const __half* gp = QKV + qbase + (size_t)(k0n + r) * QKVN + lc * 8;
                CP16(SK + nb * 8192 + soff, gp + DIM);
                CP16(SV + nb * 8192 + soff, gp + 2 * DIM);
            }
            CP_COMMIT();
        }

        uint32_t Kb = SK + kb * 8192;
        uint32_t Vb = SV + kb * 8192;

        // ---- S = Q @ K^T (Q pre-scaled) ----
        float sacc[8][4] = {};
        #pragma unroll
        for (int ks = 0; ks < 4; ks++) {
            uint32_t af[4];
            {
                int r = wm + (lane & 15);
                int c = ks * 2 + (lane >> 4);
                LDMX4(af, SQ + r * 128 + ((c ^ (r & 7)) << 4));
            }
            uint32_t bf[4][4];
            #pragma unroll
            for (int nt = 0; nt < 4; nt++) {
                int r = nt * 16 + (lane & 15);
                int c = ks * 2 + (lane >> 4);
                LDMX4(bf[nt], Kb + r * 128 + ((c ^ (r & 7)) << 4));
            }
            #pragma unroll
            for (int j = 0; j < 8; j++)
                MMA16816(sacc[j], af, bf[j >> 1][j & 1], bf[j >> 1][(j & 1) + 2]);
        }

        int lr0 = wm + groupId, lr1 = lr0 + 8;
        if (kt == qt) {   // causal mask on diagonal tile
            #pragma unroll
            for (int j = 0; j < 8; j++) {
                int c0 = j * 8 + t4 * 2;
                if (c0     > lr0) sacc[j][0] = -1e30f;
                if (c0 + 1 > lr0) sacc[j][1] = -1e30f;
                if (c0     > lr1) sacc[j][2] = -1e30f;
                if (c0 + 1 > lr1) sacc[j][3] = -1e30f;
            }
        }

        float mx0 = -1e30f, mx1 = -1e30f;
        #pragma unroll
        for (int j = 0; j < 8; j++) {
            mx0 = fmaxf(mx0, fmaxf(sacc[j][0], sacc[j][1]));
            mx1 = fmaxf(mx1, fmaxf(sacc[j][2], sacc[j][3]));
        }
        mx0 = fmaxf(mx0, __shfl_xor_sync(0xffffffffu, mx0, 1));
        mx0 = fmaxf(mx0, __shfl_xor_sync(0xffffffffu, mx0, 2));
        mx1 = fmaxf(mx1, __shfl_xor_sync(0xffffffffu, mx1, 1));
        mx1 = fmaxf(mx1, __shfl_xor_sync(0xffffffffu, mx1, 2));

        float mn0 = fmaxf(m0, mx0), mn1 = fmaxf(m1, mx1);
        float c0f = __expf(m0 - mn0), c1f = __expf(m1 - mn1);
        float s0 = 0.f, s1 = 0.f;
        uint32_t pf[8][2];   // P as A-fragment halves: pf[j][0]=(row g), pf[j][1]=(row g+8)
        #pragma unroll
        for (int j = 0; j < 8; j++) {
            float p0 = __expf(sacc[j][0] - mn0);
            float p1 = __expf(sacc[j][1] - mn0);
            float p2 = __expf(sacc[j][2] - mn1);
            float p3 = __expf(sacc[j][3] - mn1);
            s0 += p0 + p1; s1 += p2 + p3;
            __half2 h0 = __floats2half2_rn(p0, p1);
            __half2 h1 = __floats2half2_rn(p2, p3);
            pf[j][0] = *reinterpret_cast<uint32_t*>(&h0);
            pf[j][1] = *reinterpret_cast<uint32_t*>(&h1);
        }
        s0 += __shfl_xor_sync(0xffffffffu, s0, 1);
        s0 += __shfl_xor_sync(0xffffffffu, s0, 2);
        s1 += __shfl_xor_sync(0xffffffffu, s1, 1);
        s1 += __shfl_xor_sync(0xffffffffu, s1, 2);
        l0 = l0 * c0f + s0; m0 = mn0;
        l1 = l1 * c1f + s1; m1 = mn1;
        #pragma unroll
        for (int j = 0; j < 8; j++) {
            oacc[j][0] *= c0f; oacc[j][1] *= c0f;
            oacc[j][2] *= c1f; oacc[j][3] *= c1f;
        }

        // ---- O += P @ V (P from registers) ----
        #pragma unroll
        for (int ks2 = 0; ks2 < 4; ks2++) {
            uint32_t pfrag[4] = { pf[2*ks2][0], pf[2*ks2][1], pf[2*ks2+1][0], pf[2*ks2+1][1] };
            uint32_t vf[4][4];
            #pragma unroll
            for (int nt = 0; nt < 4; nt++) {
                int r = ks2 * 16 + (lane & 15);
                int c = nt * 2 + (lane >> 4);
                LDMX4T(vf[nt], Vb + r * 128 + ((c ^ (r & 7)) << 4));
            }
            #pragma unroll
            for (int j = 0; j < 8; j++)
                MMA16816(oacc[j], pfrag, vf[j >> 1][2 * (j & 1)], vf[j >> 1][2 * (j & 1) + 1]);
        }
    }

    const size_t obase = ((size_t)b * SEQ + q0) * DIM + (size_t)h * DKH;
    float inv0 = 1.f / l0, inv1 = 1.f / l1;
    int lr0 = wm + groupId, lr1 = lr0 + 8;
    #pragma unroll
    for (int j = 0; j < 8; j++) {
        int col = j * 8 + t4 * 2;
        *(__half2*)(O16 + obase + (size_t)lr0 * DIM + col) =
            __floats2half2_rn(oacc[j][0] * inv0, oacc[j][1] * inv0);
        *(__half2*)(O16 + obase + (size_t)lr1 * DIM + col) =
            __floats2half2_rn(oacc[j][2] * inv1, oacc[j][3] * inv1);
    }
}

// ---------------- launch --------------------------------------------------------------
extern "C" void kernel_launch(void* const* d_in, const int* in_sizes, int n_in,
                              void* d_out, int out_size) {
    const float* x     = (const float*)d_in[0];
    const float* ln1_g = (const float*)d_in[2];
    const float* ln1_b = (const float*)d_in[3];
    const float* ln2_g = (const float*)d_in[4];
    const float* ln2_b = (const float*)d_in[5];
    const float* Wq    = (const float*)d_in[6];
    const float* Wk    = (const float*)d_in[7];
    const float* Wv    = (const float*)d_in[8];
    const float* Wo    = (const float*)d_in[9];
    const float* Wg    = (const float*)d_in[10];
    const float* bg    = (const float*)d_in[11];
    const float* Wout  = (const float*)d_in[12];
    float* out = (float*)d_out;

    __half *h16, *qkv16, *att16, *ff16, *qkvw, *wo16, *wg16, *wout16;
    float *x1;
    cudaGetSymbolAddress((void**)&h16,    g_h16);
    cudaGetSymbolAddress((void**)&qkv16,  g_qkv16);
    cudaGetSymbolAddress((void**)&att16,  g_att16);
    cudaGetSymbolAddress((void**)&x1,     g_x1);
    cudaGetSymbolAddress((void**)&ff16,   g_ff16);
    cudaGetSymbolAddress((void**)&qkvw,   g_qkvw);
    cudaGetSymbolAddress((void**)&wo16,   g_wo);
    cudaGetSymbolAddress((void**)&wg16,   g_wg);
    cudaGetSymbolAddress((void**)&wout16, g_wout);

    const int ATTN_SMEM = 40960;
    const int GEMM_SMEM = 3 * 32768;   // 98304 (3-stage)
    cudaFuncSetAttribute(attn_kernel, cudaFuncAttributeMaxDynamicSharedMemorySize, ATTN_SMEM);
    cudaFuncSetAttribute(gemm16<1,0,0,0,1>, cudaFuncAttributeMaxDynamicSharedMemorySize, GEMM_SMEM);
    cudaFuncSetAttribute(gemm16<0,0,1,0,0>, cudaFuncAttributeMaxDynamicSharedMemorySize, GEMM_SMEM);
    cudaFuncSetAttribute(gemm16<1,0,0,1,0>, cudaFuncAttributeMaxDynamicSharedMemorySize, GEMM_SMEM);

    // weight prep: one launch (9216 blocks; Wg rows permuted for GeGLU fusion)
    wtrans_all<<<9216, dim3(32, 8)>>>(Wq, Wk, Wv, Wo, Wg, Wout,
                                      qkvw, wo16, wg16, wout16);

    // attention sublayer (pre-LN); QKV GEMM scales Q columns by 0.125
    ln_kernel<<<TOK, 256>>>(x, ln1_g, ln1_b, h16);
    gemm16<1,0,0,0,1><<<dim3(QKVN/128, TOK/128), 256, GEMM_SMEM>>>(h16, qkvw, nullptr, nullptr, qkv16, QKVN, DIM);
    attn_kernel<<<dim3(SEQ/64, BATCH*NH), 128, ATTN_SMEM>>>(qkv16, att16);
    gemm16<0,0,1,0,0><<<dim3(DIM/128, TOK/128), 256, GEMM_SMEM>>>(att16, wo16, nullptr, x, x1, DIM, DIM);

    // GeGLU FFN sublayer (pre-LN); Wg GEMM fuses bias + GeGLU, writes ff16 directly
    ln_kernel<<<TOK, 256>>>(x1, ln2_g, ln2_b, h16);
    gemm16<1,0,0,1,0><<<dim3(2*DFF/128, TOK/128), 256, GEMM_SMEM>>>(h16, wg16, bg, nullptr, ff16, 2*DFF, DIM);
    gemm16<0,0,1,0,0><<<dim3(DIM/128, TOK/128), 256, GEMM_SMEM>>>(ff16, wout16, nullptr, x1, out, DIM, DFF);
}

// round 12
// speedup vs baseline: 1.0777x; 1.0260x over previous
#include <cuda_runtime.h>
#include <cuda_fp16.h>
#include <math.h>
#include <stdint.h>

#define BATCH 4
#define SEQ   2048
#define DIM   768
#define NH    12
#define DKH   64
#define DFF   3072
#define TOK   (BATCH*SEQ)   // 8192
#define QKVN  (3*DIM)       // 2304

// Q pre-scale folded into QKV GEMM: 1/sqrt(64) * log2(e), so attention can use exp2.
#define QSCALE_F 0.18033688011112042f

// ---------------- scratch (device globals; no runtime allocation) -------------------
__device__ __half g_h16  [TOK*DIM];
__device__ __half g_qkv16[(size_t)TOK*QKVN];
__device__ __half g_att16[TOK*DIM];
__device__ float  g_x1   [(size_t)TOK*DIM];
__device__ __half g_ff16 [(size_t)TOK*DFF];
__device__ __half g_qkvw [QKVN*DIM];      // [2304,768] fp16 (W^T)
__device__ __half g_wo   [DIM*DIM];       // [768,768]
__device__ __half g_wg   [2*DFF*DIM];     // [6144,768] (val/gate interleaved per 8 rows)
__device__ __half g_wout [DIM*DFF];       // [768,3072]

// ---------------- PTX helpers (baseline ISA: cp.async, ldmatrix, mma.sync) ----------
__device__ __forceinline__ uint32_t smem_u32(const void* p) {
    uint32_t a;
    asm("{ .reg .u64 t; cvta.to.shared.u64 t, %1; cvt.u32.u64 %0, t; }" : "=r"(a) : "l"(p));
    return a;
}
#define CP16(sa, gp) asm volatile("cp.async.cg.shared.global [%0], [%1], 16;\n" :: "r"(sa), "l"(gp))
#define CP_COMMIT()  asm volatile("cp.async.commit_group;\n" ::: "memory")
#define CP_WAIT(n)   asm volatile("cp.async.wait_group %0;\n" :: "n"(n) : "memory")

#define LDMX4(r, addr) \
    asm volatile("ldmatrix.sync.aligned.m8n8.x4.shared.b16 {%0,%1,%2,%3}, [%4];" \
        : "=r"((r)[0]), "=r"((r)[1]), "=r"((r)[2]), "=r"((r)[3]) : "r"(addr))
#define LDMX4T(r, addr) \
    asm volatile("ldmatrix.sync.aligned.m8n8.x4.trans.shared.b16 {%0,%1,%2,%3}, [%4];" \
        : "=r"((r)[0]), "=r"((r)[1]), "=r"((r)[2]), "=r"((r)[3]) : "r"(addr))

#define MMA16816(d, a, b0, b1) \
    asm volatile("mma.sync.aligned.m16n8k16.row.col.f32.f16.f16.f32 " \
        "{%0,%1,%2,%3}, {%4,%5,%6,%7}, {%8,%9}, {%0,%1,%2,%3};" \
        : "+f"((d)[0]), "+f"((d)[1]), "+f"((d)[2]), "+f"((d)[3]) \
        : "r"((a)[0]), "r"((a)[1]), "r"((a)[2]), "r"((a)[3]), "r"(b0), "r"(b1))

// ---------------- fused weight prep: all 6 transposes in one launch ------------------
__global__ void wtrans_all(const float* __restrict__ Wq, const float* __restrict__ Wk,
                           const float* __restrict__ Wv, const float* __restrict__ Wo,
                           const float* __restrict__ Wg, const float* __restrict__ Wout_,
                           __half* __restrict__ qkvw, __half* __restrict__ wo16,
                           __half* __restrict__ wg16, __half* __restrict__ wout16) {
    int bid = blockIdx.x;
    const float* W; __half* Wt; int K, N, bx, by, perm = 0;
    if (bid < 1728) {                       // Wq, Wk, Wv -> qkvw
        int m = bid / 576, r = bid % 576;
        W = (m == 0) ? Wq : (m == 1) ? Wk : Wv;
        Wt = qkvw + (size_t)m * DIM * DIM; K = DIM; N = DIM;
        bx = r % 24; by = r / 24;
    } else if (bid < 2304) {                // Wo
        int r = bid - 1728; W = Wo; Wt = wo16; K = DIM; N = DIM;
        bx = r % 24; by = r / 24;
    } else if (bid < 6912) {                // Wg (permuted)
        int r = bid - 2304; W = Wg; Wt = wg16; K = DIM; N = 2 * DFF; perm = 1;
        bx = r % 192; by = r / 192;
    } else {                                // Wout
        int r = bid - 6912; W = Wout_; Wt = wout16; K = DFF; N = DIM;
        bx = r % 24; by = r / 24;
    }
    __shared__ float tile[32][33];
    int k0 = by * 32, n0 = bx * 32;
    int tx = threadIdx.x, ty = threadIdx.y;
    #pragma unroll
    for (int i = ty; i < 32; i += 8)
        tile[i][tx] = W[(size_t)(k0 + i) * N + n0 + tx];
    __syncthreads();
    #pragma unroll
    for (int i = ty; i < 32; i += 8) {
        int n = n0 + i, dr;
        if (perm) {
            int isg = n >= DFF;
            int sp = isg ? n - DFF : n;
            dr = (sp >> 3) * 16 + (isg << 3) + (sp & 7);
        } else dr = n;
        Wt[(size_t)dr * K + k0 + tx] = __float2half_rn(tile[tx][i]);
    }
}

// ---------------- LayerNorm -> fp16 (one warp per row, shuffle-only) ------------------
__global__ void ln_kernel(const float* __restrict__ x, const float* __restrict__ g,
                          const float* __restrict__ b, __half* __restrict__ out) {
    int row  = (blockIdx.x * blockDim.x + threadIdx.x) >> 5;
    int lane = threadIdx.x & 31;
    const float4* xr = (const float4*)(x + (size_t)row * DIM);   // 192 float4 per row
    float4 v[6];
    float s1 = 0.f, s2 = 0.f;
    #pragma unroll
    for (int i = 0; i < 6; i++) {
        v[i] = xr[lane + i * 32];
        s1 += v[i].x + v[i].y + v[i].z + v[i].w;
        s2 += v[i].x*v[i].x + v[i].y*v[i].y + v[i].z*v[i].z + v[i].w*v[i].w;
    }
    #pragma unroll
    for (int o = 16; o; o >>= 1) {
        s1 += __shfl_xor_sync(0xffffffffu, s1, o);
        s2 += __shfl_xor_sync(0xffffffffu, s2, o);
    }
    float mu  = s1 * (1.f / DIM);
    float var = s2 * (1.f / DIM) - mu * mu;
    float inv = rsqrtf(var + 1e-5f);
    const float4* gr = (const float4*)g;
    const float4* br = (const float4*)b;
    __half* outr = out + (size_t)row * DIM;
    #pragma unroll
    for (int i = 0; i < 6; i++) {
        int j = lane + i * 32;               // float4 index; cols 4j..4j+3
        float4 gv = gr[j], bv = br[j];
        float o0 = (v[i].x - mu) * inv * gv.x + bv.x;
        float o1 = (v[i].y - mu) * inv * gv.y + bv.y;
        float o2 = (v[i].z - mu) * inv * gv.z + bv.z;
        float o3 = (v[i].w - mu) * inv * gv.w + bv.w;
        __half2 ha = __floats2half2_rn(o0, o1);
        __half2 hb = __floats2half2_rn(o2, o3);
        uint2 u;
        u.x = *reinterpret_cast<uint32_t*>(&ha);
        u.y = *reinterpret_cast<uint32_t*>(&hb);
        *reinterpret_cast<uint2*>(outr + 4 * j) = u;
    }
}

// ---------------- HMMA fp16 GEMM: C[M,N] = A16[M,K] @ Bt16[N,K]^T ---------------------
// CTA tile 128x128, 8 warps (2m x 4n), warp tile 64x32, K-chunk 64.
// 3-stage cp.async pipeline, one barrier per chunk.
// QSCALE=1: cols < DIM scaled by QSCALE_F. GEGLU=1: (val+b)*gelu(gate+b) -> fp16.
template<int OUTH, int BIAS, int RES, int GEGLU, int QSCALE>
__global__ void __launch_bounds__(256, 2)
gemm16(const __half* __restrict__ A, const __half* __restrict__ Bt,
       const float* __restrict__ bias, const float* __restrict__ res,
       void* __restrict__ Cout, int N, int K) {
    extern __shared__ char sm[];
    uint32_t BUF = smem_u32(sm);          // stage s at BUF + s*32768: A(16K) B(16K)
    const int bm = blockIdx.y * 128, bn = blockIdx.x * 128;
    int tid = threadIdx.x, wid = tid >> 5, lane = tid & 31;
    int wm = (wid >> 2) * 64, wn = (wid & 3) * 32;

    const int NK = K >> 6;
    const int lr = tid >> 3;    // 0..31
    const int lc = tid & 7;     // 16B chunk in 128B row

    float acc[4][4][4] = {};

    // prologue: chunks 0 and 1 -> stages 0 and 1
    #pragma unroll
    for (int s = 0; s < 2; s++) {
        const __half* Ag = A  + (size_t)(bm + lr) * K + (size_t)s * 64 + lc * 8;
        const __half* Bg = Bt + (size_t)(bn + lr) * K + (size_t)s * 64 + lc * 8;
        uint32_t sa = BUF + s * 32768u;
        #pragma unroll
        for (int l = 0; l < 4; l++) {
            int r = lr + l * 32;
            uint32_t soff = r * 128 + ((lc ^ (r & 7)) << 4);
            CP16(sa + soff,         Ag + (size_t)l * 32 * K);
            CP16(sa + 16384 + soff, Bg + (size_t)l * 32 * K);
        }
        CP_COMMIT();
    }

    for (int kc = 0; kc < NK; kc++) {
        if (kc + 1 < NK) { CP_WAIT(1); } else { CP_WAIT(0); }
        __syncthreads();   // publishes chunk kc; all warps done with chunk kc-1
        if (kc + 2 < NK) {
            int st = (kc + 2) % 3;
            const __half* Ag = A  + (size_t)(bm + lr) * K + (size_t)(kc + 2) * 64 + lc * 8;
            const __half* Bg = Bt + (size_t)(bn + lr) * K + (size_t)(kc + 2) * 64 + lc * 8;
            uint32_t sa = BUF + st * 32768u;
            #pragma unroll
            for (int l = 0; l < 4; l++) {
                int r = lr + l * 32;
                uint32_t soff = r * 128 + ((lc ^ (r & 7)) << 4);
                CP16(sa + soff,         Ag + (size_t)l * 32 * K);
                CP16(sa + 16384 + soff, Bg + (size_t)l * 32 * K);
            }
            CP_COMMIT();
        }

        uint32_t Ab = BUF + (kc % 3) * 32768u;
        uint32_t Bb = Ab + 16384u;
        #pragma unroll
        for (int ks = 0; ks < 4; ks++) {
            uint32_t af[4][4];
            #pragma unroll
            for (int mt = 0; mt < 4; mt++) {
                int r = wm + mt * 16 + (lane & 15);
                int c = ks * 2 + (lane >> 4);
                LDMX4(af[mt], Ab + r * 128 + ((c ^ (r & 7)) << 4));
            }
            uint32_t bf[2][4];
            #pragma unroll
            for (int nt = 0; nt < 2; nt++) {
                int r = wn + nt * 16 + (lane & 15);
                int c = ks * 2 + (lane >> 4);
                LDMX4(bf[nt], Bb + r * 128 + ((c ^ (r & 7)) << 4));
            }
            #pragma unroll
            for (int mt = 0; mt < 4; mt++) {
                #pragma unroll
                for (int n8 = 0; n8 < 4; n8++) {
                    uint32_t b0 = bf[n8 >> 1][n8 & 1];
                    uint32_t b1 = bf[n8 >> 1][(n8 & 1) + 2];
                    MMA16816(acc[mt][n8], af[mt], b0, b1);
                }
            }
        }
    }

    int groupId = lane >> 2, t4 = lane & 3;
    if (GEGLU) {
        // fragment n8 even = val cols, n8 odd = gate cols for the same output cols
        #pragma unroll
        for (int mt = 0; mt < 4; mt++) {
            #pragma unroll
            for (int n8 = 0; n8 < 4; n8 += 2) {
                float* dv = acc[mt][n8];
                float* dg = acc[mt][n8 + 1];
                int colp = bn + wn + n8 * 8;             // permuted base, multiple of 16
                int cout = ((colp >> 4) << 3) + t4 * 2;  // output col in [0,DFF)
                float bv0 = bias[cout],       bv1 = bias[cout + 1];
                float bg0 = bias[DFF + cout], bg1 = bias[DFF + cout + 1];
                #pragma unroll
                for (int h2 = 0; h2 < 2; h2++) {
                    int row = bm + wm + mt * 16 + groupId + h2 * 8;
                    float v0 = dv[h2 * 2] + bv0, v1 = dv[h2 * 2 + 1] + bv1;
                    float g0 = dg[h2 * 2] + bg0, g1 = dg[h2 * 2 + 1] + bg1;
                    float f0 = v0 * 0.5f * g0 * (1.f + erff(g0 * 0.70710678118654752f));
                    float f1 = v1 * 0.5f * g1 * (1.f + erff(g1 * 0.70710678118654752f));
                    *(__half2*)((__half*)Cout + (size_t)row * DFF + cout) = __floats2half2_rn(f0, f1);
                }
            }
        }
        return;
    }
    #pragma unroll
    for (int mt = 0; mt < 4; mt++) {
        #pragma unroll
        for (int n8 = 0; n8 < 4; n8++) {
            float* d = acc[mt][n8];
            int col = bn + wn + n8 * 8 + t4 * 2;
            #pragma unroll
            for (int h2 = 0; h2 < 2; h2++) {
                int row = bm + wm + mt * 16 + groupId + h2 * 8;
                float v0 = d[h2 * 2], v1 = d[h2 * 2 + 1];
                if (BIAS) { v0 += bias[col]; v1 += bias[col + 1]; }
                if (RES) {
                    float2 rv = *(const float2*)(res + (size_t)row * N + col);
                    v0 += rv.x; v1 += rv.y;
                }
                if (QSCALE && col < DIM) { v0 *= QSCALE_F; v1 *= QSCALE_F; }
                if (OUTH) {
                    *(__half2*)((__half*)Cout + (size_t)row * N + col) = __floats2half2_rn(v0, v1);
                } else {
                    *(float2*)((float*)Cout + (size_t)row * N + col) = make_float2(v0, v1);
                }
            }
        }
    }
}

// ---------------- Flash attention, fp16 HMMA, causal, BQ=BK=64 ------------------------
// 4 warps x 16 q-rows. SMEM (40KB): Qs 8K | Ks[2] 16K | Vs[2] 16K. P stays in
// registers, packed IN PLACE over sacc (sacc[j][0..1] reused as the A-fragment pair).
// Q pre-scaled by 0.125*log2(e) (folded into QKV GEMM) -> softmax uses exp2.
// __launch_bounds__(128,5): cap regs at 102 so 5 CTAs/SM fit (smem allows 5).
__global__ void __launch_bounds__(128, 5)
attn_kernel(const __half* __restrict__ QKV, __half* __restrict__ O16) {
    extern __shared__ char sm[];
    uint32_t SB = smem_u32(sm);
    const uint32_t SQ = SB;
    const uint32_t SK = SB + 8192;      // + kb*8192
    const uint32_t SV = SB + 24576;     // + kb*8192

    int qt = blockIdx.x;
    int bh = blockIdx.y;
    int h = bh % NH, b = bh / NH;
    int q0 = qt * 64;
    int tid = threadIdx.x, wid = tid >> 5, lane = tid & 31;
    int wm = wid * 16;
    int groupId = lane >> 2, t4 = lane & 3;
    const size_t qbase = (size_t)b * SEQ * QKVN + (size_t)h * DKH;

    int lr8 = tid >> 3, lc = tid & 7;

    // Q tile + KV tile 0 (single group)
    #pragma unroll
    for (int l = 0; l < 4; l++) {
        int r = lr8 + l * 16;
        uint32_t soff = r * 128 + ((lc ^ (r & 7)) << 4);
        CP16(SQ + soff, QKV + qbase + (size_t)(q0 + r) * QKVN + lc * 8);
    }
    #pragma unroll
    for (int l = 0; l < 4; l++) {
        int r = lr8 + l * 16;
        uint32_t soff = r * 128 + ((lc ^ (r & 7)) << 4);
        const __half* gp = QKV + qbase + (size_t)r * QKVN + lc * 8;
        CP16(SK + soff, gp + DIM);
        CP16(SV + soff, gp + 2 * DIM);
    }
    CP_COMMIT();

    float m0 = -1e30f, m1 = -1e30f, l0 = 0.f, l1 = 0.f;
    float oacc[8][4] = {};

    for (int kt = 0; kt <= qt; kt++) {
        int kb = kt & 1;
        CP_WAIT(0);
        __syncthreads();   // publishes KV kt; all warps done with buffer kb^1
        if (kt < qt) {
            int nb = kb ^ 1;
            int k0n = (kt + 1) * 64;
            #pragma unroll
            for (int l = 0; l < 4; l++) {
                int r = lr8 + l * 16;
                uint32_t soff = r * 128 + ((lc ^ (r & 7)) << 4);
                const __half* gp = QKV + qbase + (size_t)(k0n + r) * QKVN + lc * 8;
                CP16(SK + nb * 8192 + soff, gp + DIM);
                CP16(SV + nb * 8192 + soff, gp + 2 * DIM);
            }
            CP_COMMIT();
        }

        uint32_t Kb = SK + kb * 8192;
        uint32_t Vb = SV + kb * 8192;

        // ---- S = Q @ K^T (Q pre-scaled; S in log2 domain) ----
        float sacc[8][4] = {};
        #pragma unroll
        for (int ks = 0; ks < 4; ks++) {
            uint32_t af[4];
            {
                int r = wm + (lane & 15);
                int c = ks * 2 + (lane >> 4);
                LDMX4(af, SQ + r * 128 + ((c ^ (r & 7)) << 4));
            }
            uint32_t bf[4][4];
            #pragma unroll
            for (int nt = 0; nt < 4; nt++) {
                int r = nt * 16 + (lane & 15);
                int c = ks * 2 + (lane >> 4);
                LDMX4(bf[nt], Kb + r * 128 + ((c ^ (r & 7)) << 4));
            }
            #pragma unroll
            for (int j = 0; j < 8; j++)
                MMA16816(sacc[j], af, bf[j >> 1][j & 1], bf[j >> 1][(j & 1) + 2]);
        }

        int lr0 = wm + groupId, lr1 = lr0 + 8;
        if (kt == qt) {   // causal mask on diagonal tile
            #pragma unroll
            for (int j = 0; j < 8; j++) {
                int c0 = j * 8 + t4 * 2;
                if (c0     > lr0) sacc[j][0] = -1e30f;
                if (c0 + 1 > lr0) sacc[j][1] = -1e30f;
                if (c0     > lr1) sacc[j][2] = -1e30f;
                if (c0 + 1 > lr1) sacc[j][3] = -1e30f;
            }
        }

        float mx0 = -1e30f, mx1 = -1e30f;
        #pragma unroll
        for (int j = 0; j < 8; j++) {
            mx0 = fmaxf(mx0, fmaxf(sacc[j][0], sacc[j][1]));
            mx1 = fmaxf(mx1, fmaxf(sacc[j][2], sacc[j][3]));
        }
        mx0 = fmaxf(mx0, __shfl_xor_sync(0xffffffffu, mx0, 1));
        mx0 = fmaxf(mx0, __shfl_xor_sync(0xffffffffu, mx0, 2));
        mx1 = fmaxf(mx1, __shfl_xor_sync(0xffffffffu, mx1, 1));
        mx1 = fmaxf(mx1, __shfl_xor_sync(0xffffffffu, mx1, 2));

        float mn0 = fmaxf(m0, mx0), mn1 = fmaxf(m1, mx1);
        float c0f = exp2f(m0 - mn0), c1f = exp2f(m1 - mn1);
        float s0 = 0.f, s1 = 0.f;
        // P packed IN PLACE: sacc[j][0] <- pack(p(row g) cols 0,1); sacc[j][1] <- pack(row g+8)
        #pragma unroll
        for (int j = 0; j < 8; j++) {
            float p0 = exp2f(sacc[j][0] - mn0);
            float p1 = exp2f(sacc[j][1] - mn0);
            float p2 = exp2f(sacc[j][2] - mn1);
            float p3 = exp2f(sacc[j][3] - mn1);
            s0 += p0 + p1; s1 += p2 + p3;
            __half2 h0 = __floats2half2_rn(p0, p1);
            __half2 h1 = __floats2half2_rn(p2, p3);
            sacc[j][0] = __uint_as_float(*reinterpret_cast<uint32_t*>(&h0));
            sacc[j][1] = __uint_as_float(*reinterpret_cast<uint32_t*>(&h1));
        }
        s0 += __shfl_xor_sync(0xffffffffu, s0, 1);
        s0 += __shfl_xor_sync(0xffffffffu, s0, 2);
        s1 += __shfl_xor_sync(0xffffffffu, s1, 1);
        s1 += __shfl_xor_sync(0xffffffffu, s1, 2);
        l0 = l0 * c0f + s0; m0 = mn0;
        l1 = l1 * c1f + s1; m1 = mn1;
        #pragma unroll
        for (int j = 0; j < 8; j++) {
            oacc[j][0] *= c0f; oacc[j][1] *= c0f;
            oacc[j][2] *= c1f; oacc[j][3] *= c1f;
        }

        // ---- O += P @ V (P from registers, packed in sacc) ----
        #pragma unroll
        for (int ks2 = 0; ks2 < 4; ks2++) {
            uint32_t pfrag[4] = {
                __float_as_uint(sacc[2*ks2][0]),   __float_as_uint(sacc[2*ks2][1]),
                __float_as_uint(sacc[2*ks2+1][0]), __float_as_uint(sacc[2*ks2+1][1]) };
            uint32_t vf[4][4];
            #pragma unroll
            for (int nt = 0; nt < 4; nt++) {
                int r = ks2 * 16 + (lane & 15);
                int c = nt * 2 + (lane >> 4);
                LDMX4T(vf[nt], Vb + r * 128 + ((c ^ (r & 7)) << 4));
            }
            #pragma unroll
            for (int j = 0; j < 8; j++)
                MMA16816(oacc[j], pfrag, vf[j >> 1][2 * (j & 1)], vf[j >> 1][2 * (j & 1) + 1]);
        }
    }

    const size_t obase = ((size_t)b * SEQ + q0) * DIM + (size_t)h * DKH;
    float inv0 = 1.f / l0, inv1 = 1.f / l1;
    int lr0 = wm + groupId, lr1 = lr0 + 8;
    #pragma unroll
    for (int j = 0; j < 8; j++) {
        int col = j * 8 + t4 * 2;
        *(__half2*)(O16 + obase + (size_t)lr0 * DIM + col) =
            __floats2half2_rn(oacc[j][0] * inv0, oacc[j][1] * inv0);
        *(__half2*)(O16 + obase + (size_t)lr1 * DIM + col) =
            __floats2half2_rn(oacc[j][2] * inv1, oacc[j][3] * inv1);
    }
}

// ---------------- launch --------------------------------------------------------------
extern "C" void kernel_launch(void* const* d_in, const int* in_sizes, int n_in,
                              void* d_out, int out_size) {
    const float* x     = (const float*)d_in[0];
    const float* ln1_g = (const float*)d_in[2];
    const float* ln1_b = (const float*)d_in[3];
    const float* ln2_g = (const float*)d_in[4];
    const float* ln2_b = (const float*)d_in[5];
    const float* Wq    = (const float*)d_in[6];
    const float* Wk    = (const float*)d_in[7];
    const float* Wv    = (const float*)d_in[8];
    const float* Wo    = (const float*)d_in[9];
    const float* Wg    = (const float*)d_in[10];
    const float* bg    = (const float*)d_in[11];
    const float* Wout  = (const float*)d_in[12];
    float* out = (float*)d_out;

    __half *h16, *qkv16, *att16, *ff16, *qkvw, *wo16, *wg16, *wout16;
    float *x1;
    cudaGetSymbolAddress((void**)&h16,    g_h16);
    cudaGetSymbolAddress((void**)&qkv16,  g_qkv16);
    cudaGetSymbolAddress((void**)&att16,  g_att16);
    cudaGetSymbolAddress((void**)&x1,     g_x1);
    cudaGetSymbolAddress((void**)&ff16,   g_ff16);
    cudaGetSymbolAddress((void**)&qkvw,   g_qkvw);
    cudaGetSymbolAddress((void**)&wo16,   g_wo);
    cudaGetSymbolAddress((void**)&wg16,   g_wg);
    cudaGetSymbolAddress((void**)&wout16, g_wout);

    const int ATTN_SMEM = 40960;
    const int GEMM_SMEM = 3 * 32768;   // 98304 (3-stage)
    cudaFuncSetAttribute(attn_kernel, cudaFuncAttributeMaxDynamicSharedMemorySize, ATTN_SMEM);
    cudaFuncSetAttribute(gemm16<1,0,0,0,1>, cudaFuncAttributeMaxDynamicSharedMemorySize, GEMM_SMEM);
    cudaFuncSetAttribute(gemm16<0,0,1,0,0>, cudaFuncAttributeMaxDynamicSharedMemorySize, GEMM_SMEM);
    cudaFuncSetAttribute(gemm16<1,0,0,1,0>, cudaFuncAttributeMaxDynamicSharedMemorySize, GEMM_SMEM);

    // weight prep: one launch (9216 blocks; Wg rows permuted for GeGLU fusion)
    wtrans_all<<<9216, dim3(32, 8)>>>(Wq, Wk, Wv, Wo, Wg, Wout,
                                      qkvw, wo16, wg16, wout16);

    // attention sublayer (pre-LN); QKV GEMM scales Q columns by 0.125*log2(e)
    ln_kernel<<<TOK/8, 256>>>(x, ln1_g, ln1_b, h16);
    gemm16<1,0,0,0,1><<<dim3(QKVN/128, TOK/128), 256, GEMM_SMEM>>>(h16, qkvw, nullptr, nullptr, qkv16, QKVN, DIM);
    attn_kernel<<<dim3(SEQ/64, BATCH*NH), 128, ATTN_SMEM>>>(qkv16, att16);
    gemm16<0,0,1,0,0><<<dim3(DIM/128, TOK/128), 256, GEMM_SMEM>>>(att16, wo16, nullptr, x, x1, DIM, DIM);

    // GeGLU FFN sublayer (pre-LN); Wg GEMM fuses bias + GeGLU, writes ff16 directly
    ln_kernel<<<TOK/8, 256>>>(x1, ln2_g, ln2_b, h16);
    gemm16<1,0,0,1,0><<<dim3(2*DFF/128, TOK/128), 256, GEMM_SMEM>>>(h16, wg16, bg, nullptr, ff16, 2*DFF, DIM);
    gemm16<0,0,1,0,0><<<dim3(DIM/128, TOK/128), 256, GEMM_SMEM>>>(ff16, wout16, nullptr, x1, out, DIM, DFF);
}

// round 14
// speedup vs baseline: 1.1143x; 1.0339x over previous
#include <cuda_runtime.h>
#include <cuda_fp16.h>
#include <math.h>
#include <stdint.h>

#define BATCH 4
#define SEQ   2048
#define DIM   768
#define NH    12
#define DKH   64
#define DFF   3072
#define TOK   (BATCH*SEQ)   // 8192
#define QKVN  (3*DIM)       // 2304
#define NQT   (SEQ/64)      // 32 q-tiles per (b,h)
#define NBH   (BATCH*NH)    // 48
#define NTILE (NQT*NBH)     // 1536
#define AGRID 740           // 5 CTAs/SM x 148 SMs
#define ALEFT (NTILE - 2*AGRID)   // 56

// Q pre-scale folded into QKV GEMM: 1/sqrt(64) * log2(e), so attention can use exp2.
#define QSCALE_F 0.18033688011112042f

// ---------------- scratch (device globals; no runtime allocation) -------------------
__device__ __half g_h16  [TOK*DIM];
__device__ __half g_qkv16[(size_t)TOK*QKVN];
__device__ __half g_att16[TOK*DIM];
__device__ float  g_x1   [(size_t)TOK*DIM];
__device__ __half g_ff16 [(size_t)TOK*DFF];
__device__ __half g_qkvw [QKVN*DIM];      // [2304,768] fp16 (W^T)
__device__ __half g_wo   [DIM*DIM];       // [768,768]
__device__ __half g_wg   [2*DFF*DIM];     // [6144,768] (val/gate interleaved per 8 rows)
__device__ __half g_wout [DIM*DFF];       // [768,3072]

// ---------------- PTX helpers (baseline ISA: cp.async, ldmatrix, mma.sync) ----------
__device__ __forceinline__ uint32_t smem_u32(const void* p) {
    uint32_t a;
    asm("{ .reg .u64 t; cvta.to.shared.u64 t, %1; cvt.u32.u64 %0, t; }" : "=r"(a) : "l"(p));
    return a;
}
#define CP16(sa, gp) asm volatile("cp.async.cg.shared.global [%0], [%1], 16;\n" :: "r"(sa), "l"(gp))
#define CP_COMMIT()  asm volatile("cp.async.commit_group;\n" ::: "memory")
#define CP_WAIT(n)   asm volatile("cp.async.wait_group %0;\n" :: "n"(n) : "memory")

#define LDMX4(r, addr) \
    asm volatile("ldmatrix.sync.aligned.m8n8.x4.shared.b16 {%0,%1,%2,%3}, [%4];" \
        : "=r"((r)[0]), "=r"((r)[1]), "=r"((r)[2]), "=r"((r)[3]) : "r"(addr))
#define LDMX4T(r, addr) \
    asm volatile("ldmatrix.sync.aligned.m8n8.x4.trans.shared.b16 {%0,%1,%2,%3}, [%4];" \
        : "=r"((r)[0]), "=r"((r)[1]), "=r"((r)[2]), "=r"((r)[3]) : "r"(addr))

#define MMA16816(d, a, b0, b1) \
    asm volatile("mma.sync.aligned.m16n8k16.row.col.f32.f16.f16.f32 " \
        "{%0,%1,%2,%3}, {%4,%5,%6,%7}, {%8,%9}, {%0,%1,%2,%3};" \
        : "+f"((d)[0]), "+f"((d)[1]), "+f"((d)[2]), "+f"((d)[3]) \
        : "r"((a)[0]), "r"((a)[1]), "r"((a)[2]), "r"((a)[3]), "r"(b0), "r"(b1))

// ---------------- fused weight prep: all 6 transposes in one launch ------------------
__global__ void wtrans_all(const float* __restrict__ Wq, const float* __restrict__ Wk,
                           const float* __restrict__ Wv, const float* __restrict__ Wo,
                           const float* __restrict__ Wg, const float* __restrict__ Wout_,
                           __half* __restrict__ qkvw, __half* __restrict__ wo16,
                           __half* __restrict__ wg16, __half* __restrict__ wout16) {
    int bid = blockIdx.x;
    const float* W; __half* Wt; int K, N, bx, by, perm = 0;
    if (bid < 1728) {                       // Wq, Wk, Wv -> qkvw
        int m = bid / 576, r = bid % 576;
        W = (m == 0) ? Wq : (m == 1) ? Wk : Wv;
        Wt = qkvw + (size_t)m * DIM * DIM; K = DIM; N = DIM;
        bx = r % 24; by = r / 24;
    } else if (bid < 2304) {                // Wo
        int r = bid - 1728; W = Wo; Wt = wo16; K = DIM; N = DIM;
        bx = r % 24; by = r / 24;
    } else if (bid < 6912) {                // Wg (permuted)
        int r = bid - 2304; W = Wg; Wt = wg16; K = DIM; N = 2 * DFF; perm = 1;
        bx = r % 192; by = r / 192;
    } else {                                // Wout
        int r = bid - 6912; W = Wout_; Wt = wout16; K = DFF; N = DIM;
        bx = r % 24; by = r / 24;
    }
    __shared__ float tile[32][33];
    int k0 = by * 32, n0 = bx * 32;
    int tx = threadIdx.x, ty = threadIdx.y;
    #pragma unroll
    for (int i = ty; i < 32; i += 8)
        tile[i][tx] = W[(size_t)(k0 + i) * N + n0 + tx];
    __syncthreads();
    #pragma unroll
    for (int i = ty; i < 32; i += 8) {
        int n = n0 + i, dr;
        if (perm) {
            int isg = n >= DFF;
            int sp = isg ? n - DFF : n;
            dr = (sp >> 3) * 16 + (isg << 3) + (sp & 7);
        } else dr = n;
        Wt[(size_t)dr * K + k0 + tx] = __float2half_rn(tile[tx][i]);
    }
}

// ---------------- LayerNorm -> fp16 (one warp per row, shuffle-only) ------------------
__global__ void ln_kernel(const float* __restrict__ x, const float* __restrict__ g,
                          const float* __restrict__ b, __half* __restrict__ out) {
    int row  = (blockIdx.x * blockDim.x + threadIdx.x) >> 5;
    int lane = threadIdx.x & 31;
    const float4* xr = (const float4*)(x + (size_t)row * DIM);   // 192 float4 per row
    float4 v[6];
    float s1 = 0.f, s2 = 0.f;
    #pragma unroll
    for (int i = 0; i < 6; i++) {
        v[i] = xr[lane + i * 32];
        s1 += v[i].x + v[i].y + v[i].z + v[i].w;
        s2 += v[i].x*v[i].x + v[i].y*v[i].y + v[i].z*v[i].z + v[i].w*v[i].w;
    }
    #pragma unroll
    for (int o = 16; o; o >>= 1) {
        s1 += __shfl_xor_sync(0xffffffffu, s1, o);
        s2 += __shfl_xor_sync(0xffffffffu, s2, o);
    }
    float mu  = s1 * (1.f / DIM);
    float var = s2 * (1.f / DIM) - mu * mu;
    float inv = rsqrtf(var + 1e-5f);
    const float4* gr = (const float4*)g;
    const float4* br = (const float4*)b;
    __half* outr = out + (size_t)row * DIM;
    #pragma unroll
    for (int i = 0; i < 6; i++) {
        int j = lane + i * 32;               // float4 index; cols 4j..4j+3
        float4 gv = gr[j], bv = br[j];
        float o0 = (v[i].x - mu) * inv * gv.x + bv.x;
        float o1 = (v[i].y - mu) * inv * gv.y + bv.y;
        float o2 = (v[i].z - mu) * inv * gv.z + bv.z;
        float o3 = (v[i].w - mu) * inv * gv.w + bv.w;
        __half2 ha = __floats2half2_rn(o0, o1);
        __half2 hb = __floats2half2_rn(o2, o3);
        uint2 u;
        u.x = *reinterpret_cast<uint32_t*>(&ha);
        u.y = *reinterpret_cast<uint32_t*>(&hb);
        *reinterpret_cast<uint2*>(outr + 4 * j) = u;
    }
}

// ---------------- HMMA fp16 GEMM: C[M,N] = A16[M,K] @ Bt16[N,K]^T ---------------------
// CTA tile 128x128, 8 warps (2m x 4n), warp tile 64x32, K-chunk 64.
// 3-stage cp.async pipeline, one barrier per chunk.
// QSCALE=1: cols < DIM scaled by QSCALE_F. GEGLU=1: (val+b)*gelu(gate+b) -> fp16.
template<int OUTH, int BIAS, int RES, int GEGLU, int QSCALE>
__global__ void __launch_bounds__(256, 2)
gemm16(const __half* __restrict__ A, const __half* __restrict__ Bt,
       const float* __restrict__ bias, const float* __restrict__ res,
       void* __restrict__ Cout, int N, int K) {
    extern __shared__ char sm[];
    uint32_t BUF = smem_u32(sm);          // stage s at BUF + s*32768: A(16K) B(16K)
    const int bm = blockIdx.y * 128, bn = blockIdx.x * 128;
    int tid = threadIdx.x, wid = tid >> 5, lane = tid & 31;
    int wm = (wid >> 2) * 64, wn = (wid & 3) * 32;

    const int NK = K >> 6;
    const int lr = tid >> 3;    // 0..31
    const int lc = tid & 7;     // 16B chunk in 128B row

    float acc[4][4][4] = {};

    // prologue: chunks 0 and 1 -> stages 0 and 1
    #pragma unroll
    for (int s = 0; s < 2; s++) {
        const __half* Ag = A  + (size_t)(bm + lr) * K + (size_t)s * 64 + lc * 8;
        const __half* Bg = Bt + (size_t)(bn + lr) * K + (size_t)s * 64 + lc * 8;
        uint32_t sa = BUF + s * 32768u;
        #pragma unroll
        for (int l = 0; l < 4; l++) {
            int r = lr + l * 32;
            uint32_t soff = r * 128 + ((lc ^ (r & 7)) << 4);
            CP16(sa + soff,         Ag + (size_t)l * 32 * K);
            CP16(sa + 16384 + soff, Bg + (size_t)l * 32 * K);
        }
        CP_COMMIT();
    }

    for (int kc = 0; kc < NK; kc++) {
        if (kc + 1 < NK) { CP_WAIT(1); } else { CP_WAIT(0); }
        __syncthreads();   // publishes chunk kc; all warps done with chunk kc-1
        if (kc + 2 < NK) {
            int st = (kc + 2) % 3;
            const __half* Ag = A  + (size_t)(bm + lr) * K + (size_t)(kc + 2) * 64 + lc * 8;
            const __half* Bg = Bt + (size_t)(bn + lr) * K + (size_t)(kc + 2) * 64 + lc * 8;
            uint32_t sa = BUF + st * 32768u;
            #pragma unroll
            for (int l = 0; l < 4; l++) {
                int r = lr + l * 32;
                uint32_t soff = r * 128 + ((lc ^ (r & 7)) << 4);
                CP16(sa + soff,         Ag + (size_t)l * 32 * K);
                CP16(sa + 16384 + soff, Bg + (size_t)l * 32 * K);
            }
            CP_COMMIT();
        }

        uint32_t Ab = BUF + (kc % 3) * 32768u;
        uint32_t Bb = Ab + 16384u;
        #pragma unroll
        for (int ks = 0; ks < 4; ks++) {
            uint32_t af[4][4];
            #pragma unroll
            for (int mt = 0; mt < 4; mt++) {
                int r = wm + mt * 16 + (lane & 15);
                int c = ks * 2 + (lane >> 4);
                LDMX4(af[mt], Ab + r * 128 + ((c ^ (r & 7)) << 4));
            }
            uint32_t bf[2][4];
            #pragma unroll
            for (int nt = 0; nt < 2; nt++) {
                int r = wn + nt * 16 + (lane & 15);
                int c = ks * 2 + (lane >> 4);
                LDMX4(bf[nt], Bb + r * 128 + ((c ^ (r & 7)) << 4));
            }
            #pragma unroll
            for (int mt = 0; mt < 4; mt++) {
                #pragma unroll
                for (int n8 = 0; n8 < 4; n8++) {
                    uint32_t b0 = bf[n8 >> 1][n8 & 1];
                    uint32_t b1 = bf[n8 >> 1][(n8 & 1) + 2];
                    MMA16816(acc[mt][n8], af[mt], b0, b1);
                }
            }
        }
    }

    int groupId = lane >> 2, t4 = lane & 3;
    if (GEGLU) {
        // fragment n8 even = val cols, n8 odd = gate cols for the same output cols
        #pragma unroll
        for (int mt = 0; mt < 4; mt++) {
            #pragma unroll
            for (int n8 = 0; n8 < 4; n8 += 2) {
                float* dv = acc[mt][n8];
                float* dg = acc[mt][n8 + 1];
                int colp = bn + wn + n8 * 8;             // permuted base, multiple of 16
                int cout = ((colp >> 4) << 3) + t4 * 2;  // output col in [0,DFF)
                float bv0 = bias[cout],       bv1 = bias[cout + 1];
                float bg0 = bias[DFF + cout], bg1 = bias[DFF + cout + 1];
                #pragma unroll
                for (int h2 = 0; h2 < 2; h2++) {
                    int row = bm + wm + mt * 16 + groupId + h2 * 8;
                    float v0 = dv[h2 * 2] + bv0, v1 = dv[h2 * 2 + 1] + bv1;
                    float g0 = dg[h2 * 2] + bg0, g1 = dg[h2 * 2 + 1] + bg1;
                    float f0 = v0 * 0.5f * g0 * (1.f + erff(g0 * 0.70710678118654752f));
                    float f1 = v1 * 0.5f * g1 * (1.f + erff(g1 * 0.70710678118654752f));
                    *(__half2*)((__half*)Cout + (size_t)row * DFF + cout) = __floats2half2_rn(f0, f1);
                }
            }
        }
        return;
    }
    #pragma unroll
    for (int mt = 0; mt < 4; mt++) {
        #pragma unroll
        for (int n8 = 0; n8 < 4; n8++) {
            float* d = acc[mt][n8];
            int col = bn + wn + n8 * 8 + t4 * 2;
            #pragma unroll
            for (int h2 = 0; h2 < 2; h2++) {
                int row = bm + wm + mt * 16 + groupId + h2 * 8;
                float v0 = d[h2 * 2], v1 = d[h2 * 2 + 1];
                if (BIAS) { v0 += bias[col]; v1 += bias[col + 1]; }
                if (RES) {
                    float2 rv = *(const float2*)(res + (size_t)row * N + col);
                    v0 += rv.x; v1 += rv.y;
                }
                if (QSCALE && col < DIM) { v0 *= QSCALE_F; v1 *= QSCALE_F; }
                if (OUTH) {
                    *(__half2*)((__half*)Cout + (size_t)row * N + col) = __floats2half2_rn(v0, v1);
                } else {
                    *(float2*)((float*)Cout + (size_t)row * N + col) = make_float2(v0, v1);
                }
            }
        }
    }
}

// ---------------- Flash attention, fp16 HMMA, causal, BQ=BK=64 ------------------------
// Static LPT schedule: tiles sorted by descending work (tile k -> qt = 31 - k/48,
// bh = k % 48). Grid = 740 = one full residency wave (5 CTA/SM); CTA p processes
// tiles {p, 1479-p, 1480+p(if p<56)} -> per-slot work ~34-36 tile-iters, no tail.
// 4 warps x 16 q-rows. SMEM (40KB): Qs 8K | Ks[2] 16K | Vs[2] 16K. P packed in
// place over sacc. Q pre-scaled by 0.125*log2(e) -> softmax uses exp2.
__global__ void __launch_bounds__(128, 5)
attn_kernel(const __half* __restrict__ QKV, __half* __restrict__ O16) {
    extern __shared__ char sm[];
    uint32_t SB = smem_u32(sm);
    const uint32_t SQ = SB;
    const uint32_t SK = SB + 8192;      // + kb*8192
    const uint32_t SV = SB + 24576;     // + kb*8192

    int tid = threadIdx.x, wid = tid >> 5, lane = tid & 31;
    int wm = wid * 16;
    int groupId = lane >> 2, t4 = lane & 3;
    int lr8 = tid >> 3, lc = tid & 7;

    int p = blockIdx.x;
    int tlist[3];
    int ntl = 2;
    tlist[0] = p;
    tlist[1] = (2 * AGRID - 1) - p;           // 1479 - p (pairs longest with shortest)
    if (p < ALEFT) { tlist[2] = 2 * AGRID + p; ntl = 3; }   // 1480..1535

    for (int ti = 0; ti < ntl; ti++) {
        int k = tlist[ti];
        int qt = (NQT - 1) - (k / NBH);
        int bh = k - (k / NBH) * NBH;
        int h = bh % NH, b = bh / NH;
        int q0 = qt * 64;
        const size_t qbase = (size_t)b * SEQ * QKVN + (size_t)h * DKH;

        __syncthreads();   // previous tile fully consumed before SMEM refill

        // Q tile + KV tile 0 (single group)
        #pragma unroll
        for (int l = 0; l < 4; l++) {
            int r = lr8 + l * 16;
            uint32_t soff = r * 128 + ((lc ^ (r & 7)) << 4);
            CP16(SQ + soff, QKV + qbase + (size_t)(q0 + r) * QKVN + lc * 8);
        }
        #pragma unroll
        for (int l = 0; l < 4; l++) {
            int r = lr8 + l * 16;
            uint32_t soff = r * 128 + ((lc ^ (r & 7)) << 4);
            const __half* gp = QKV + qbase + (size_t)r * QKVN + lc * 8;
            CP16(SK + soff, gp + DIM);
            CP16(SV + soff, gp + 2 * DIM);
        }
        CP_COMMIT();

        float m0 = -1e30f, m1 = -1e30f, l0 = 0.f, l1 = 0.f;
        float oacc[8][4] = {};

        for (int kt = 0; kt <= qt; kt++) {
            int kb = kt & 1;
            CP_WAIT(0);
            __syncthreads();   // publishes KV kt; all warps done with buffer kb^1
            if (kt < qt) {
                int nb = kb ^ 1;
                int k0n = (kt + 1) * 64;
                #pragma unroll
                for (int l = 0; l < 4; l++) {
                    int r = lr8 + l * 16;
                    uint32_t soff = r * 128 + ((lc ^ (r & 7)) << 4);
                    const __half* gp = QKV + qbase + (size_t)(k0n + r) * QKVN + lc * 8;
                    CP16(SK + nb * 8192 + soff, gp + DIM);
                    CP16(SV + nb * 8192 + soff, gp + 2 * DIM);
                }
                CP_COMMIT();
            }

            uint32_t Kb = SK + kb * 8192;
            uint32_t Vb = SV + kb * 8192;

            // ---- S = Q @ K^T (Q pre-scaled; S in log2 domain) ----
            float sacc[8][4] = {};
            #pragma unroll
            for (int ks = 0; ks < 4; ks++) {
                uint32_t af[4];
                {
                    int r = wm + (lane & 15);
                    int c = ks * 2 + (lane >> 4);
                    LDMX4(af, SQ + r * 128 + ((c ^ (r & 7)) << 4));
                }
                uint32_t bf[4][4];
                #pragma unroll
                for (int nt = 0; nt < 4; nt++) {
                    int r = nt * 16 + (lane & 15);
                    int c = ks * 2 + (lane >> 4);
                    LDMX4(bf[nt], Kb + r * 128 + ((c ^ (r & 7)) << 4));
                }
                #pragma unroll
                for (int j = 0; j < 8; j++)
                    MMA16816(sacc[j], af, bf[j >> 1][j & 1], bf[j >> 1][(j & 1) + 2]);
            }

            int lr0 = wm + groupId, lr1 = lr0 + 8;
            if (kt == qt) {   // causal mask on diagonal tile
                #pragma unroll
                for (int j = 0; j < 8; j++) {
                    int c0 = j * 8 + t4 * 2;
                    if (c0     > lr0) sacc[j][0] = -1e30f;
                    if (c0 + 1 > lr0) sacc[j][1] = -1e30f;
                    if (c0     > lr1) sacc[j][2] = -1e30f;
                    if (c0 + 1 > lr1) sacc[j][3] = -1e30f;
                }
            }

            float mx0 = -1e30f, mx1 = -1e30f;
            #pragma unroll
            for (int j = 0; j < 8; j++) {
                mx0 = fmaxf(mx0, fmaxf(sacc[j][0], sacc[j][1]));
                mx1 = fmaxf(mx1, fmaxf(sacc[j][2], sacc[j][3]));
            }
            mx0 = fmaxf(mx0, __shfl_xor_sync(0xffffffffu, mx0, 1));
            mx0 = fmaxf(mx0, __shfl_xor_sync(0xffffffffu, mx0, 2));
            mx1 = fmaxf(mx1, __shfl_xor_sync(0xffffffffu, mx1, 1));
            mx1 = fmaxf(mx1, __shfl_xor_sync(0xffffffffu, mx1, 2));

            float mn0 = fmaxf(m0, mx0), mn1 = fmaxf(m1, mx1);
            float c0f = exp2f(m0 - mn0), c1f = exp2f(m1 - mn1);
            float s0 = 0.f, s1 = 0.f;
            // P packed IN PLACE: sacc[j][0] <- pack(row g), sacc[j][1] <- pack(row g+8)
            #pragma unroll
            for (int j = 0; j < 8; j++) {
                float p0 = exp2f(sacc[j][0] - mn0);
                float p1 = exp2f(sacc[j][1] - mn0);
                float p2 = exp2f(sacc[j][2] - mn1);
                float p3 = exp2f(sacc[j][3] - mn1);
                s0 += p0 + p1; s1 += p2 + p3;
                __half2 h0 = __floats2half2_rn(p0, p1);
                __half2 h1 = __floats2half2_rn(p2, p3);
                sacc[j][0] = __uint_as_float(*reinterpret_cast<uint32_t*>(&h0));
                sacc[j][1] = __uint_as_float(*reinterpret_cast<uint32_t*>(&h1));
            }
            s0 += __shfl_xor_sync(0xffffffffu, s0, 1);
            s0 += __shfl_xor_sync(0xffffffffu, s0, 2);
            s1 += __shfl_xor_sync(0xffffffffu, s1, 1);
            s1 += __shfl_xor_sync(0xffffffffu, s1, 2);
            l0 = l0 * c0f + s0; m0 = mn0;
            l1 = l1 * c1f + s1; m1 = mn1;
            #pragma unroll
            for (int j = 0; j < 8; j++) {
                oacc[j][0] *= c0f; oacc[j][1] *= c0f;
                oacc[j][2] *= c1f; oacc[j][3] *= c1f;
            }

            // ---- O += P @ V (P from registers, packed in sacc) ----
            #pragma unroll
            for (int ks2 = 0; ks2 < 4; ks2++) {
                uint32_t pfrag[4] = {
                    __float_as_uint(sacc[2*ks2][0]),   __float_as_uint(sacc[2*ks2][1]),
                    __float_as_uint(sacc[2*ks2+1][0]), __float_as_uint(sacc[2*ks2+1][1]) };
                uint32_t vf[4][4];
                #pragma unroll
                for (int nt = 0; nt < 4; nt++) {
                    int r = ks2 * 16 + (lane & 15);
                    int c = nt * 2 + (lane >> 4);
                    LDMX4T(vf[nt], Vb + r * 128 + ((c ^ (r & 7)) << 4));
                }
                #pragma unroll
                for (int j = 0; j < 8; j++)
                    MMA16816(oacc[j], pfrag, vf[j >> 1][2 * (j & 1)], vf[j >> 1][2 * (j & 1) + 1]);
            }
        }

        const size_t obase = ((size_t)b * SEQ + q0) * DIM + (size_t)h * DKH;
        float inv0 = 1.f / l0, inv1 = 1.f / l1;
        int lr0 = wm + groupId, lr1 = lr0 + 8;
        #pragma unroll
        for (int j = 0; j < 8; j++) {
            int col = j * 8 + t4 * 2;
            *(__half2*)(O16 + obase + (size_t)lr0 * DIM + col) =
                __floats2half2_rn(oacc[j][0] * inv0, oacc[j][1] * inv0);
            *(__half2*)(O16 + obase + (size_t)lr1 * DIM + col) =
                __floats2half2_rn(oacc[j][2] * inv1, oacc[j][3] * inv1);
        }
    }
}

// ---------------- launch --------------------------------------------------------------
extern "C" void kernel_launch(void* const* d_in, const int* in_sizes, int n_in,
                              void* d_out, int out_size) {
    const float* x     = (const float*)d_in[0];
    const float* ln1_g = (const float*)d_in[2];
    const float* ln1_b = (const float*)d_in[3];
    const float* ln2_g = (const float*)d_in[4];
    const float* ln2_b = (const float*)d_in[5];
    const float* Wq    = (const float*)d_in[6];
    const float* Wk    = (const float*)d_in[7];
    const float* Wv    = (const float*)d_in[8];
    const float* Wo    = (const float*)d_in[9];
    const float* Wg    = (const float*)d_in[10];
    const float* bg    = (const float*)d_in[11];
    const float* Wout  = (const float*)d_in[12];
    float* out = (float*)d_out;

    __half *h16, *qkv16, *att16, *ff16, *qkvw, *wo16, *wg16, *wout16;
    float *x1;
    cudaGetSymbolAddress((void**)&h16,    g_h16);
    cudaGetSymbolAddress((void**)&qkv16,  g_qkv16);
    cudaGetSymbolAddress((void**)&att16,  g_att16);
    cudaGetSymbolAddress((void**)&x1,     g_x1);
    cudaGetSymbolAddress((void**)&ff16,   g_ff16);
    cudaGetSymbolAddress((void**)&qkvw,   g_qkvw);
    cudaGetSymbolAddress((void**)&wo16,   g_wo);
    cudaGetSymbolAddress((void**)&wg16,   g_wg);
    cudaGetSymbolAddress((void**)&wout16, g_wout);

    const int ATTN_SMEM = 40960;
    const int GEMM_SMEM = 3 * 32768;   // 98304 (3-stage)
    cudaFuncSetAttribute(attn_kernel, cudaFuncAttributeMaxDynamicSharedMemorySize, ATTN_SMEM);
    cudaFuncSetAttribute(gemm16<1,0,0,0,1>, cudaFuncAttributeMaxDynamicSharedMemorySize, GEMM_SMEM);
    cudaFuncSetAttribute(gemm16<0,0,1,0,0>, cudaFuncAttributeMaxDynamicSharedMemorySize, GEMM_SMEM);
    cudaFuncSetAttribute(gemm16<1,0,0,1,0>, cudaFuncAttributeMaxDynamicSharedMemorySize, GEMM_SMEM);

    // weight prep: one launch (9216 blocks; Wg rows permuted for GeGLU fusion)
    wtrans_all<<<9216, dim3(32, 8)>>>(Wq, Wk, Wv, Wo, Wg, Wout,
                                      qkvw, wo16, wg16, wout16);

    // attention sublayer (pre-LN); QKV GEMM scales Q columns by 0.125*log2(e)
    ln_kernel<<<TOK/8, 256>>>(x, ln1_g, ln1_b, h16);
    gemm16<1,0,0,0,1><<<dim3(QKVN/128, TOK/128), 256, GEMM_SMEM>>>(h16, qkvw, nullptr, nullptr, qkv16, QKVN, DIM);
    attn_kernel<<<AGRID, 128, ATTN_SMEM>>>(qkv16, att16);
    gemm16<0,0,1,0,0><<<dim3(DIM/128, TOK/128), 256, GEMM_SMEM>>>(att16, wo16, nullptr, x, x1, DIM, DIM);

    // GeGLU FFN sublayer (pre-LN); Wg GEMM fuses bias + GeGLU, writes ff16 directly
    ln_kernel<<<TOK/8, 256>>>(x1, ln2_g, ln2_b, h16);
    gemm16<1,0,0,1,0><<<dim3(2*DFF/128, TOK/128), 256, GEMM_SMEM>>>(h16, wg16, bg, nullptr, ff16, 2*DFF, DIM);
    gemm16<0,0,1,0,0><<<dim3(DIM/128, TOK/128), 256, GEMM_SMEM>>>(ff16, wout16, nullptr, x1, out, DIM, DFF);
}

// round 15
// speedup vs baseline: 1.1326x; 1.0164x over previous
#include <cuda_runtime.h>
#include <cuda_fp16.h>
#include <math.h>
#include <stdint.h>

#define BATCH 4
#define SEQ   2048
#define DIM   768
#define NH    12
#define DKH   64
#define DFF   3072
#define TOK   (BATCH*SEQ)   // 8192
#define QKVN  (3*DIM)       // 2304
#define NQT   (SEQ/64)      // 32 q-tiles per (b,h)
#define NBH   (BATCH*NH)    // 48
#define NTILE (NQT*NBH)     // 1536
#define AGRID 740           // 5 CTAs/SM x 148 SMs
#define ALEFT (NTILE - 2*AGRID)   // 56

// Q pre-scale folded into QKV GEMM: 1/sqrt(64) * log2(e), so attention can use exp2.
#define QSCALE_F 0.18033688011112042f

// ---------------- scratch (device globals; no runtime allocation) -------------------
__device__ __half g_h16  [TOK*DIM];
__device__ __half g_qkv16[(size_t)TOK*QKVN];
__device__ __half g_att16[TOK*DIM];
__device__ float  g_x1   [(size_t)TOK*DIM];
__device__ __half g_ff16 [(size_t)TOK*DFF];
__device__ __half g_qkvw [QKVN*DIM];      // [2304,768] fp16 (W^T)
__device__ __half g_wo   [DIM*DIM];       // [768,768]
__device__ __half g_wg   [2*DFF*DIM];     // [6144,768] (val/gate interleaved per 8 rows)
__device__ __half g_wout [DIM*DFF];       // [768,3072]

// ---------------- PTX helpers (baseline ISA: cp.async, ldmatrix, mma.sync) ----------
__device__ __forceinline__ uint32_t smem_u32(const void* p) {
    uint32_t a;
    asm("{ .reg .u64 t; cvta.to.shared.u64 t, %1; cvt.u32.u64 %0, t; }" : "=r"(a) : "l"(p));
    return a;
}
#define CP16(sa, gp) asm volatile("cp.async.cg.shared.global [%0], [%1], 16;\n" :: "r"(sa), "l"(gp))
#define CP_COMMIT()  asm volatile("cp.async.commit_group;\n" ::: "memory")
#define CP_WAIT(n)   asm volatile("cp.async.wait_group %0;\n" :: "n"(n) : "memory")

#define LDMX4(r, addr) \
    asm volatile("ldmatrix.sync.aligned.m8n8.x4.shared.b16 {%0,%1,%2,%3}, [%4];" \
        : "=r"((r)[0]), "=r"((r)[1]), "=r"((r)[2]), "=r"((r)[3]) : "r"(addr))
#define LDMX4T(r, addr) \
    asm volatile("ldmatrix.sync.aligned.m8n8.x4.trans.shared.b16 {%0,%1,%2,%3}, [%4];" \
        : "=r"((r)[0]), "=r"((r)[1]), "=r"((r)[2]), "=r"((r)[3]) : "r"(addr))

#define MMA16816(d, a, b0, b1) \
    asm volatile("mma.sync.aligned.m16n8k16.row.col.f32.f16.f16.f32 " \
        "{%0,%1,%2,%3}, {%4,%5,%6,%7}, {%8,%9}, {%0,%1,%2,%3};" \
        : "+f"((d)[0]), "+f"((d)[1]), "+f"((d)[2]), "+f"((d)[3]) \
        : "r"((a)[0]), "r"((a)[1]), "r"((a)[2]), "r"((a)[3]), "r"(b0), "r"(b1))

// ---------------- fused weight prep: all 6 transposes in one launch ------------------
__global__ void wtrans_all(const float* __restrict__ Wq, const float* __restrict__ Wk,
                           const float* __restrict__ Wv, const float* __restrict__ Wo,
                           const float* __restrict__ Wg, const float* __restrict__ Wout_,
                           __half* __restrict__ qkvw, __half* __restrict__ wo16,
                           __half* __restrict__ wg16, __half* __restrict__ wout16) {
    int bid = blockIdx.x;
    const float* W; __half* Wt; int K, N, bx, by, perm = 0;
    if (bid < 1728) {                       // Wq, Wk, Wv -> qkvw
        int m = bid / 576, r = bid % 576;
        W = (m == 0) ? Wq : (m == 1) ? Wk : Wv;
        Wt = qkvw + (size_t)m * DIM * DIM; K = DIM; N = DIM;
        bx = r % 24; by = r / 24;
    } else if (bid < 2304) {                // Wo
        int r = bid - 1728; W = Wo; Wt = wo16; K = DIM; N = DIM;
        bx = r % 24; by = r / 24;
    } else if (bid < 6912) {                // Wg (permuted)
        int r = bid - 2304; W = Wg; Wt = wg16; K = DIM; N = 2 * DFF; perm = 1;
        bx = r % 192; by = r / 192;
    } else {                                // Wout
        int r = bid - 6912; W = Wout_; Wt = wout16; K = DFF; N = DIM;
        bx = r % 24; by = r / 24;
    }
    __shared__ float tile[32][33];
    int k0 = by * 32, n0 = bx * 32;
    int tx = threadIdx.x, ty = threadIdx.y;
    #pragma unroll
    for (int i = ty; i < 32; i += 8)
        tile[i][tx] = W[(size_t)(k0 + i) * N + n0 + tx];
    __syncthreads();
    #pragma unroll
    for (int i = ty; i < 32; i += 8) {
        int n = n0 + i, dr;
        if (perm) {
            int isg = n >= DFF;
            int sp = isg ? n - DFF : n;
            dr = (sp >> 3) * 16 + (isg << 3) + (sp & 7);
        } else dr = n;
        Wt[(size_t)dr * K + k0 + tx] = __float2half_rn(tile[tx][i]);
    }
}

// ---------------- LayerNorm -> fp16 (one warp per row, shuffle-only) ------------------
__global__ void ln_kernel(const float* __restrict__ x, const float* __restrict__ g,
                          const float* __restrict__ b, __half* __restrict__ out) {
    int row  = (blockIdx.x * blockDim.x + threadIdx.x) >> 5;
    int lane = threadIdx.x & 31;
    const float4* xr = (const float4*)(x + (size_t)row * DIM);   // 192 float4 per row
    float4 v[6];
    float s1 = 0.f, s2 = 0.f;
    #pragma unroll
    for (int i = 0; i < 6; i++) {
        v[i] = xr[lane + i * 32];
        s1 += v[i].x + v[i].y + v[i].z + v[i].w;
        s2 += v[i].x*v[i].x + v[i].y*v[i].y + v[i].z*v[i].z + v[i].w*v[i].w;
    }
    #pragma unroll
    for (int o = 16; o; o >>= 1) {
        s1 += __shfl_xor_sync(0xffffffffu, s1, o);
        s2 += __shfl_xor_sync(0xffffffffu, s2, o);
    }
    float mu  = s1 * (1.f / DIM);
    float var = s2 * (1.f / DIM) - mu * mu;
    float inv = rsqrtf(var + 1e-5f);
    const float4* gr = (const float4*)g;
    const float4* br = (const float4*)b;
    __half* outr = out + (size_t)row * DIM;
    #pragma unroll
    for (int i = 0; i < 6; i++) {
        int j = lane + i * 32;               // float4 index; cols 4j..4j+3
        float4 gv = gr[j], bv = br[j];
        float o0 = (v[i].x - mu) * inv * gv.x + bv.x;
        float o1 = (v[i].y - mu) * inv * gv.y + bv.y;
        float o2 = (v[i].z - mu) * inv * gv.z + bv.z;
        float o3 = (v[i].w - mu) * inv * gv.w + bv.w;
        __half2 ha = __floats2half2_rn(o0, o1);
        __half2 hb = __floats2half2_rn(o2, o3);
        uint2 u;
        u.x = *reinterpret_cast<uint32_t*>(&ha);
        u.y = *reinterpret_cast<uint32_t*>(&hb);
        *reinterpret_cast<uint2*>(outr + 4 * j) = u;
    }
}

// ---------------- HMMA fp16 GEMM: C[M,N] = A16[M,K] @ Bt16[N,K]^T ---------------------
// CTA tile 128x128, 8 warps (2m x 4n), warp tile 64x32, K-chunk 64.
// 3-stage cp.async pipeline, one barrier per chunk.
// QSCALE=1: cols < DIM scaled by QSCALE_F. GEGLU=1: (val+b)*gelu(gate+b) -> fp16.
template<int OUTH, int BIAS, int RES, int GEGLU, int QSCALE>
__global__ void __launch_bounds__(256, 2)
gemm16(const __half* __restrict__ A, const __half* __restrict__ Bt,
       const float* __restrict__ bias, const float* __restrict__ res,
       void* __restrict__ Cout, int N, int K) {
    extern __shared__ char sm[];
    uint32_t BUF = smem_u32(sm);          // stage s at BUF + s*32768: A(16K) B(16K)
    const int bm = blockIdx.y * 128, bn = blockIdx.x * 128;
    int tid = threadIdx.x, wid = tid >> 5, lane = tid & 31;
    int wm = (wid >> 2) * 64, wn = (wid & 3) * 32;

    const int NK = K >> 6;
    const int lr = tid >> 3;    // 0..31
    const int lc = tid & 7;     // 16B chunk in 128B row

    float acc[4][4][4] = {};

    // prologue: chunks 0 and 1 -> stages 0 and 1
    #pragma unroll
    for (int s = 0; s < 2; s++) {
        const __half* Ag = A  + (size_t)(bm + lr) * K + (size_t)s * 64 + lc * 8;
        const __half* Bg = Bt + (size_t)(bn + lr) * K + (size_t)s * 64 + lc * 8;
        uint32_t sa = BUF + s * 32768u;
        #pragma unroll
        for (int l = 0; l < 4; l++) {
            int r = lr + l * 32;
            uint32_t soff = r * 128 + ((lc ^ (r & 7)) << 4);
            CP16(sa + soff,         Ag + (size_t)l * 32 * K);
            CP16(sa + 16384 + soff, Bg + (size_t)l * 32 * K);
        }
        CP_COMMIT();
    }

    for (int kc = 0; kc < NK; kc++) {
        if (kc + 1 < NK) { CP_WAIT(1); } else { CP_WAIT(0); }
        __syncthreads();   // publishes chunk kc; all warps done with chunk kc-1
        if (kc + 2 < NK) {
            int st = (kc + 2) % 3;
            const __half* Ag = A  + (size_t)(bm + lr) * K + (size_t)(kc + 2) * 64 + lc * 8;
            const __half* Bg = Bt + (size_t)(bn + lr) * K + (size_t)(kc + 2) * 64 + lc * 8;
            uint32_t sa = BUF + st * 32768u;
            #pragma unroll
            for (int l = 0; l < 4; l++) {
                int r = lr + l * 32;
                uint32_t soff = r * 128 + ((lc ^ (r & 7)) << 4);
                CP16(sa + soff,         Ag + (size_t)l * 32 * K);
                CP16(sa + 16384 + soff, Bg + (size_t)l * 32 * K);
            }
            CP_COMMIT();
        }

        uint32_t Ab = BUF + (kc % 3) * 32768u;
        uint32_t Bb = Ab + 16384u;
        #pragma unroll
        for (int ks = 0; ks < 4; ks++) {
            uint32_t af[4][4];
            #pragma unroll
            for (int mt = 0; mt < 4; mt++) {
                int r = wm + mt * 16 + (lane & 15);
                int c = ks * 2 + (lane >> 4);
                LDMX4(af[mt], Ab + r * 128 + ((c ^ (r & 7)) << 4));
            }
            uint32_t bf[2][4];
            #pragma unroll
            for (int nt = 0; nt < 2; nt++) {
                int r = wn + nt * 16 + (lane & 15);
                int c = ks * 2 + (lane >> 4);
                LDMX4(bf[nt], Bb + r * 128 + ((c ^ (r & 7)) << 4));
            }
            #pragma unroll
            for (int mt = 0; mt < 4; mt++) {
                #pragma unroll
                for (int n8 = 0; n8 < 4; n8++) {
                    uint32_t b0 = bf[n8 >> 1][n8 & 1];
                    uint32_t b1 = bf[n8 >> 1][(n8 & 1) + 2];
                    MMA16816(acc[mt][n8], af[mt], b0, b1);
                }
            }
        }
    }

    int groupId = lane >> 2, t4 = lane & 3;
    if (GEGLU) {
        // fragment n8 even = val cols, n8 odd = gate cols for the same output cols
        #pragma unroll
        for (int mt = 0; mt < 4; mt++) {
            #pragma unroll
            for (int n8 = 0; n8 < 4; n8 += 2) {
                float* dv = acc[mt][n8];
                float* dg = acc[mt][n8 + 1];
                int colp = bn + wn + n8 * 8;             // permuted base, multiple of 16
                int cout = ((colp >> 4) << 3) + t4 * 2;  // output col in [0,DFF)
                float bv0 = bias[cout],       bv1 = bias[cout + 1];
                float bg0 = bias[DFF + cout], bg1 = bias[DFF + cout + 1];
                #pragma unroll
                for (int h2 = 0; h2 < 2; h2++) {
                    int row = bm + wm + mt * 16 + groupId + h2 * 8;
                    float v0 = dv[h2 * 2] + bv0, v1 = dv[h2 * 2 + 1] + bv1;
                    float g0 = dg[h2 * 2] + bg0, g1 = dg[h2 * 2 + 1] + bg1;
                    float f0 = v0 * 0.5f * g0 * (1.f + erff(g0 * 0.70710678118654752f));
                    float f1 = v1 * 0.5f * g1 * (1.f + erff(g1 * 0.70710678118654752f));
                    *(__half2*)((__half*)Cout + (size_t)row * DFF + cout) = __floats2half2_rn(f0, f1);
                }
            }
        }
        return;
    }
    #pragma unroll
    for (int mt = 0; mt < 4; mt++) {
        #pragma unroll
        for (int n8 = 0; n8 < 4; n8++) {
            float* d = acc[mt][n8];
            int col = bn + wn + n8 * 8 + t4 * 2;
            #pragma unroll
            for (int h2 = 0; h2 < 2; h2++) {
                int row = bm + wm + mt * 16 + groupId + h2 * 8;
                float v0 = d[h2 * 2], v1 = d[h2 * 2 + 1];
                if (BIAS) { v0 += bias[col]; v1 += bias[col + 1]; }
                if (RES) {
                    float2 rv = *(const float2*)(res + (size_t)row * N + col);
                    v0 += rv.x; v1 += rv.y;
                }
                if (QSCALE && col < DIM) { v0 *= QSCALE_F; v1 *= QSCALE_F; }
                if (OUTH) {
                    *(__half2*)((__half*)Cout + (size_t)row * N + col) = __floats2half2_rn(v0, v1);
                } else {
                    *(float2*)((float*)Cout + (size_t)row * N + col) = make_float2(v0, v1);
                }
            }
        }
    }
}

// ---------------- Flash attention, fp16 HMMA, causal, BQ=BK=64 ------------------------
// Static LPT schedule over 740 CTAs (5/SM): CTA p -> tiles {p, 1479-p, 1480+p(if p<56)}.
// 4 warps x 16 q-rows. SMEM (40KB): Qs 8K | Ks[2] 16K | Vs[2] 16K.
// P computed with ex2.approx.f16x2 (packed fp16, half the MUFU ops) and kept in
// registers (in place over sacc). Row sums l accumulated by an extra ones-MMA
// (B fragment = 1.0) -> no FADD/shuffle reduction, denominator consistent with
// the fp16 P used in the numerator. Q pre-scaled by 0.125*log2(e).
__global__ void __launch_bounds__(128, 5)
attn_kernel(const __half* __restrict__ QKV, __half* __restrict__ O16) {
    extern __shared__ char sm[];
    uint32_t SB = smem_u32(sm);
    const uint32_t SQ = SB;
    const uint32_t SK = SB + 8192;      // + kb*8192
    const uint32_t SV = SB + 24576;     // + kb*8192
    const uint32_t ONES = 0x3C003C00u;  // half2(1.0, 1.0)

    int tid = threadIdx.x, wid = tid >> 5, lane = tid & 31;
    int wm = wid * 16;
    int groupId = lane >> 2, t4 = lane & 3;
    int lr8 = tid >> 3, lc = tid & 7;

    int p = blockIdx.x;
    int tlist[3];
    int ntl = 2;
    tlist[0] = p;
    tlist[1] = (2 * AGRID - 1) - p;           // 1479 - p (pairs longest with shortest)
    if (p < ALEFT) { tlist[2] = 2 * AGRID + p; ntl = 3; }   // 1480..1535

    for (int ti = 0; ti < ntl; ti++) {
        int k = tlist[ti];
        int qt = (NQT - 1) - (k / NBH);
        int bh = k - (k / NBH) * NBH;
        int h = bh % NH, b = bh / NH;
        int q0 = qt * 64;
        const size_t qbase = (size_t)b * SEQ * QKVN + (size_t)h * DKH;

        __syncthreads();   // previous tile fully consumed before SMEM refill

        // Q tile + KV tile 0 (single group)
        #pragma unroll
        for (int l = 0; l < 4; l++) {
            int r = lr8 + l * 16;
            uint32_t soff = r * 128 + ((lc ^ (r & 7)) << 4);
            CP16(SQ + soff, QKV + qbase + (size_t)(q0 + r) * QKVN + lc * 8);
        }
        #pragma unroll
        for (int l = 0; l < 4; l++) {
            int r = lr8 + l * 16;
            uint32_t soff = r * 128 + ((lc ^ (r & 7)) << 4);
            const __half* gp = QKV + qbase + (size_t)r * QKVN + lc * 8;
            CP16(SK + soff, gp + DIM);
            CP16(SV + soff, gp + 2 * DIM);
        }
        CP_COMMIT();

        float m0 = -1e30f, m1 = -1e30f;
        float lacc[4] = {};      // ones-MMA accumulator: [0]=row g sum, [2]=row g+8 sum
        float oacc[8][4] = {};

        for (int kt = 0; kt <= qt; kt++) {
            int kb = kt & 1;
            CP_WAIT(0);
            __syncthreads();   // publishes KV kt; all warps done with buffer kb^1
            if (kt < qt) {
                int nb = kb ^ 1;
                int k0n = (kt + 1) * 64;
                #pragma unroll
                for (int l = 0; l < 4; l++) {
                    int r = lr8 + l * 16;
                    uint32_t soff = r * 128 + ((lc ^ (r & 7)) << 4);
                    const __half* gp = QKV + qbase + (size_t)(k0n + r) * QKVN + lc * 8;
                    CP16(SK + nb * 8192 + soff, gp + DIM);
                    CP16(SV + nb * 8192 + soff, gp + 2 * DIM);
                }
                CP_COMMIT();
            }

            uint32_t Kb = SK + kb * 8192;
            uint32_t Vb = SV + kb * 8192;

            // ---- S = Q @ K^T (Q pre-scaled; S in log2 domain) ----
            float sacc[8][4] = {};
            #pragma unroll
            for (int ks = 0; ks < 4; ks++) {
                uint32_t af[4];
                {
                    int r = wm + (lane & 15);
                    int c = ks * 2 + (lane >> 4);
                    LDMX4(af, SQ + r * 128 + ((c ^ (r & 7)) << 4));
                }
                uint32_t bf[4][4];
                #pragma unroll
                for (int nt = 0; nt < 4; nt++) {
                    int r = nt * 16 + (lane & 15);
                    int c = ks * 2 + (lane >> 4);
                    LDMX4(bf[nt], Kb + r * 128 + ((c ^ (r & 7)) << 4));
                }
                #pragma unroll
                for (int j = 0; j < 8; j++)
                    MMA16816(sacc[j], af, bf[j >> 1][j & 1], bf[j >> 1][(j & 1) + 2]);
            }

            int lr0 = wm + groupId, lr1 = lr0 + 8;
            if (kt == qt) {   // causal mask on diagonal tile
                #pragma unroll
                for (int j = 0; j < 8; j++) {
                    int c0 = j * 8 + t4 * 2;
                    if (c0     > lr0) sacc[j][0] = -1e30f;
                    if (c0 + 1 > lr0) sacc[j][1] = -1e30f;
                    if (c0     > lr1) sacc[j][2] = -1e30f;
                    if (c0 + 1 > lr1) sacc[j][3] = -1e30f;
                }
            }

            float mx0 = -1e30f, mx1 = -1e30f;
            #pragma unroll
            for (int j = 0; j < 8; j++) {
                mx0 = fmaxf(mx0, fmaxf(sacc[j][0], sacc[j][1]));
                mx1 = fmaxf(mx1, fmaxf(sacc[j][2], sacc[j][3]));
            }
            mx0 = fmaxf(mx0, __shfl_xor_sync(0xffffffffu, mx0, 1));
            mx0 = fmaxf(mx0, __shfl_xor_sync(0xffffffffu, mx0, 2));
            mx1 = fmaxf(mx1, __shfl_xor_sync(0xffffffffu, mx1, 1));
            mx1 = fmaxf(mx1, __shfl_xor_sync(0xffffffffu, mx1, 2));

            float mn0 = fmaxf(m0, mx0), mn1 = fmaxf(m1, mx1);
            float c0f = exp2f(m0 - mn0), c1f = exp2f(m1 - mn1);
            m0 = mn0; m1 = mn1;
            // P via ex2.approx.f16x2: packed fp16 pairs, stored in place over sacc.
            // sacc[j][0] <- pack(p row g, cols 2t4..2t4+1); sacc[j][1] <- pack(row g+8).
            #pragma unroll
            for (int j = 0; j < 8; j++) {
                float a0 = sacc[j][0] - mn0, a1 = sacc[j][1] - mn0;
                float a2 = sacc[j][2] - mn1, a3 = sacc[j][3] - mn1;
                uint32_t xp0, xp1, pp0, pp1;
                asm("cvt.rn.f16x2.f32 %0, %1, %2;" : "=r"(xp0) : "f"(a1), "f"(a0));
                asm("cvt.rn.f16x2.f32 %0, %1, %2;" : "=r"(xp1) : "f"(a3), "f"(a2));
                asm("ex2.approx.f16x2 %0, %1;" : "=r"(pp0) : "r"(xp0));
                asm("ex2.approx.f16x2 %0, %1;" : "=r"(pp1) : "r"(xp1));
                sacc[j][0] = __uint_as_float(pp0);
                sacc[j][1] = __uint_as_float(pp1);
            }
            // rescale O and l accumulators by the correction factors
            #pragma unroll
            for (int j = 0; j < 8; j++) {
                oacc[j][0] *= c0f; oacc[j][1] *= c0f;
                oacc[j][2] *= c1f; oacc[j][3] *= c1f;
            }
            lacc[0] *= c0f; lacc[1] *= c0f;
            lacc[2] *= c1f; lacc[3] *= c1f;

            // ---- O += P @ V; l += P @ ones (P from registers, packed in sacc) ----
            #pragma unroll
            for (int ks2 = 0; ks2 < 4; ks2++) {
                uint32_t pfrag[4] = {
                    __float_as_uint(sacc[2*ks2][0]),   __float_as_uint(sacc[2*ks2][1]),
                    __float_as_uint(sacc[2*ks2+1][0]), __float_as_uint(sacc[2*ks2+1][1]) };
                MMA16816(lacc, pfrag, ONES, ONES);
                uint32_t vf[4][4];
                #pragma unroll
                for (int nt = 0; nt < 4; nt++) {
                    int r = ks2 * 16 + (lane & 15);
                    int c = nt * 2 + (lane >> 4);
                    LDMX4T(vf[nt], Vb + r * 128 + ((c ^ (r & 7)) << 4));
                }
                #pragma unroll
                for (int j = 0; j < 8; j++)
                    MMA16816(oacc[j], pfrag, vf[j >> 1][2 * (j & 1)], vf[j >> 1][2 * (j & 1) + 1]);
            }
        }

        const size_t obase = ((size_t)b * SEQ + q0) * DIM + (size_t)h * DKH;
        float inv0 = 1.f / lacc[0], inv1 = 1.f / lacc[2];
        int lr0 = wm + groupId, lr1 = lr0 + 8;
        #pragma unroll
        for (int j = 0; j < 8; j++) {
            int col = j * 8 + t4 * 2;
            *(__half2*)(O16 + obase + (size_t)lr0 * DIM + col) =
                __floats2half2_rn(oacc[j][0] * inv0, oacc[j][1] * inv0);
            *(__half2*)(O16 + obase + (size_t)lr1 * DIM + col) =
                __floats2half2_rn(oacc[j][2] * inv1, oacc[j][3] * inv1);
        }
    }
}

// ---------------- launch --------------------------------------------------------------
extern "C" void kernel_launch(void* const* d_in, const int* in_sizes, int n_in,
                              void* d_out, int out_size) {
    const float* x     = (const float*)d_in[0];
    const float* ln1_g = (const float*)d_in[2];
    const float* ln1_b = (const float*)d_in[3];
    const float* ln2_g = (const float*)d_in[4];
    const float* ln2_b = (const float*)d_in[5];
    const float* Wq    = (const float*)d_in[6];
    const float* Wk    = (const float*)d_in[7];
    const float* Wv    = (const float*)d_in[8];
    const float* Wo    = (const float*)d_in[9];
    const float* Wg    = (const float*)d_in[10];
    const float* bg    = (const float*)d_in[11];
    const float* Wout  = (const float*)d_in[12];
    float* out = (float*)d_out;

    __half *h16, *qkv16, *att16, *ff16, *qkvw, *wo16, *wg16, *wout16;
    float *x1;
    cudaGetSymbolAddress((void**)&h16,    g_h16);
    cudaGetSymbolAddress((void**)&qkv16,  g_qkv16);
    cudaGetSymbolAddress((void**)&att16,  g_att16);
    cudaGetSymbolAddress((void**)&x1,     g_x1);
    cudaGetSymbolAddress((void**)&ff16,   g_ff16);
    cudaGetSymbolAddress((void**)&qkvw,   g_qkvw);
    cudaGetSymbolAddress((void**)&wo16,   g_wo);
    cudaGetSymbolAddress((void**)&wg16,   g_wg);
    cudaGetSymbolAddress((void**)&wout16, g_wout);

    const int ATTN_SMEM = 40960;
    const int GEMM_SMEM = 3 * 32768;   // 98304 (3-stage)
    cudaFuncSetAttribute(attn_kernel, cudaFuncAttributeMaxDynamicSharedMemorySize, ATTN_SMEM);
    cudaFuncSetAttribute(gemm16<1,0,0,0,1>, cudaFuncAttributeMaxDynamicSharedMemorySize, GEMM_SMEM);
    cudaFuncSetAttribute(gemm16<0,0,1,0,0>, cudaFuncAttributeMaxDynamicSharedMemorySize, GEMM_SMEM);
    cudaFuncSetAttribute(gemm16<1,0,0,1,0>, cudaFuncAttributeMaxDynamicSharedMemorySize, GEMM_SMEM);

    // weight prep: one launch (9216 blocks; Wg rows permuted for GeGLU fusion)
    wtrans_all<<<9216, dim3(32, 8)>>>(Wq, Wk, Wv, Wo, Wg, Wout,
                                      qkvw, wo16, wg16, wout16);

    // attention sublayer (pre-LN); QKV GEMM scales Q columns by 0.125*log2(e)
    ln_kernel<<<TOK/8, 256>>>(x, ln1_g, ln1_b, h16);
    gemm16<1,0,0,0,1><<<dim3(QKVN/128, TOK/128), 256, GEMM_SMEM>>>(h16, qkvw, nullptr, nullptr, qkv16, QKVN, DIM);
    attn_kernel<<<AGRID, 128, ATTN_SMEM>>>(qkv16, att16);
    gemm16<0,0,1,0,0><<<dim3(DIM/128, TOK/128), 256, GEMM_SMEM>>>(att16, wo16, nullptr, x, x1, DIM, DIM);

    // GeGLU FFN sublayer (pre-LN); Wg GEMM fuses bias + GeGLU, writes ff16 directly
    ln_kernel<<<TOK/8, 256>>>(x1, ln2_g, ln2_b, h16);
    gemm16<1,0,0,1,0><<<dim3(2*DFF/128, TOK/128), 256, GEMM_SMEM>>>(h16, wg16, bg, nullptr, ff16, 2*DFF, DIM);
    gemm16<0,0,1,0,0><<<dim3(DIM/128, TOK/128), 256, GEMM_SMEM>>>(ff16, wout16, nullptr, x1, out, DIM, DFF);
}